// round 8
// baseline (speedup 1.0000x reference)
#include <cuda_runtime.h>
#include <cuda_fp16.h>
#include <cstdint>

#define BATCH 32
#define T_TOTAL 4096
#define DM 256
#define SN 64
#define NCLS 5
#define L 64
#define MT 16
#define TOTAL_CTAS (MT * DM)

// ---- gmem precomputed operands (pre-swizzled fp16) ----
__device__ __half g_x[BATCH * T_TOTAL];
__device__ __half g_P[DM * 4096];
__device__ __half g_M[DM * 4096];
__device__ __half g_Q[DM * 4096];
__device__ float g_beta[DM * L], g_zeta[DM * SN], g_aL[DM * SN];
__device__ float g_pool[BATCH * DM * 2];
__device__ unsigned int g_ctr = 0;

// ---- smem layout (bytes) ----
#define OFF_BETA 0
#define OFF_WP   256
#define OFF_X    512               /* 128 x 128B fp16 */
#define OFF_SF   16896             /* shared F (MMA1 out) then S (seeds): 128 x 128B */
#define OFF_U    33280             /* P then M: 64 x 128B */
#define OFF_Q    41472             /* 64 x 128B */
#define SMEM_BYTES 49664

__device__ __forceinline__ uint32_t smem_u32(const void* p) {
    uint32_t a;
    asm("{ .reg .u64 t; cvta.to.shared.u64 t, %1; cvt.u32.u64 %0, t; }" : "=r"(a) : "l"(p));
    return a;
}
#define CP16(dst, src) asm volatile("cp.async.cg.shared.global [%0], [%1], 16;" :: "r"(dst), "l"(src))
#define CP_COMMIT()    asm volatile("cp.async.commit_group;" ::: "memory")
#define CP_WAIT0()     asm volatile("cp.async.wait_group 0;" ::: "memory")

__device__ __forceinline__ void ldsm4(uint32_t addr, uint32_t r[4]) {
    asm volatile("ldmatrix.sync.aligned.m8n8.x4.shared.b16 {%0,%1,%2,%3}, [%4];"
                 : "=r"(r[0]), "=r"(r[1]), "=r"(r[2]), "=r"(r[3]) : "r"(addr));
}
__device__ __forceinline__ void mma_f16(float c[4], const uint32_t a[4], uint32_t b0, uint32_t b1) {
    asm volatile("mma.sync.aligned.m16n8k16.row.col.f32.f16.f16.f32 "
                 "{%0,%1,%2,%3}, {%4,%5,%6,%7}, {%8,%9}, {%0,%1,%2,%3};"
                 : "+f"(c[0]), "+f"(c[1]), "+f"(c[2]), "+f"(c[3])
                 : "r"(a[0]), "r"(a[1]), "r"(a[2]), "r"(a[3]), "r"(b0), "r"(b1));
}
// swizzled elem index within a 128B-row fp16 tile
__device__ __forceinline__ int swzi(int row, int col) {
    return ((row * 128 + col * 2) ^ ((row & 7) << 4)) >> 1;
}

// single-product fp16 matmul-accumulate: C[16 x 64] += A(16xK64) * B(64xK64)^T
__device__ __forceinline__ void mm1(float C[8][4], uint32_t aBase, uint32_t bBase,
                                    int lane, int row0) {
    const int arow = row0 + (lane & 15);
    const uint32_t abase = (uint32_t)arow * 128;
    const uint32_t axor = (uint32_t)(arow & 7) << 4;
    const uint32_t ak16 = ((lane >> 4) & 1) * 16;
    const int brow = ((lane >> 3) & 2) * 4 + (lane & 7);
    const uint32_t bxor = (uint32_t)(brow & 7) << 4;
    const uint32_t bk16 = ((lane >> 3) & 1) * 16;
    #pragma unroll
    for (int kc = 0; kc < 4; kc++) {
        uint32_t a[4];
        ldsm4(aBase + abase + ((ak16 + kc * 32) ^ axor), a);
        #pragma unroll
        for (int j = 0; j < 4; j++) {
            uint32_t boff = (uint32_t)(j * 16 + brow) * 128 + ((bk16 + kc * 32) ^ bxor);
            uint32_t b[4];
            ldsm4(bBase + boff, b);
            mma_f16(C[2 * j],     a, b[0], b[1]);
            mma_f16(C[2 * j + 1], a, b[2], b[3]);
        }
    }
}

// ---------------- merged prep: x->fp16 swizzle (blocks 0-127) + per-d tiles (128-383) ----------------
__global__ void prep(const float* __restrict__ x,
                     const float* __restrict__ w_in, const float* __restrict__ b_in,
                     const float* __restrict__ A_diag, const float* __restrict__ B_in,
                     const float* __restrict__ C_out, const float* __restrict__ D_skip) {
    const int tid = threadIdx.x;
    if (blockIdx.x < 128) {
        int e = (blockIdx.x * 256 + tid) * 4;
        float4 v = *reinterpret_cast<const float4*>(x + e);
        int b = e >> 12, t = e & 4095;
        int rg = b * 64 + (t >> 6), col = t & 63;
        int boff = rg * 128 + ((col * 2) ^ ((rg & 7) << 4));
        __half2 p0 = __floats2half2_rn(v.x, v.y);
        __half2 p1 = __floats2half2_rn(v.z, v.w);
        char* p = (char*)g_x + boff;
        *(__half2*)p = p0;
        *(__half2*)(p + 4) = p1;
        return;
    }
    const int d = blockIdx.x - 128;
    const int n = tid & 63, q = tid >> 6;
    __shared__ float gmat[64][65];
    __shared__ float Kp[64][4];
    __shared__ float Ksm[64];
    __shared__ float zp[4][64];

    float a = A_diag[d * 64 + n];
    float g = B_in[d * 64 + n] * C_out[d * 64 + n];
    float a2 = a * a, a4 = a2 * a2, a8 = a4 * a4, a16 = a8 * a8;
    float a32 = a16 * a16, a48 = a32 * a16, a64v = a32 * a32;
    float s = (q == 0) ? 1.f : ((q == 1) ? a16 : ((q == 2) ? a32 : a48));

    {   // P[n][tau] = a^(63-tau); zeta partial
        float p = s, zs = 0.f;
        #pragma unroll
        for (int j = 0; j < 16; j++) {
            int e = q * 16 + j, tau = 63 - e;
            g_P[d * 4096 + swzi(n, tau)] = __float2half_rn(p);
            zs += p; p *= a;
        }
        zp[q][n] = zs;
    }
    {   // Q[i][n] = g*a^(i+1)
        float t = g * s * a;
        #pragma unroll
        for (int j = 0; j < 16; j++) {
            int i = q * 16 + j;
            g_Q[d * 4096 + swzi(i, n)] = __float2half_rn(t);
            t *= a;
        }
    }
    {   // gmat[delta][n] = g*a^delta
        float u = g * s;
        #pragma unroll
        for (int j = 0; j < 16; j++) { gmat[q * 16 + j][n] = u; u *= a; }
    }
    __syncthreads();
    if (q == 0) {
        g_zeta[d * 64 + n] = zp[0][n] + zp[1][n] + zp[2][n] + zp[3][n];
        g_aL[d * 64 + n] = a64v;
    }
    {   // K[delta] partial over n
        float ss = 0.f;
        #pragma unroll
        for (int j = 0; j < 16; j++) ss += gmat[n][q * 16 + j];
        Kp[n][q] = ss;
    }
    __syncthreads();
    if (tid < 64) Ksm[tid] = Kp[tid][0] + Kp[tid][1] + Kp[tid][2] + Kp[tid][3];
    __syncthreads();
    float w = w_in[d], bb = b_in[d], dsk = D_skip[d];
    if (tid < 64) {
        float kap = 0.f;
        for (int dd = 0; dd <= tid; dd++) kap += Ksm[dd];
        g_beta[d * 64 + tid] = bb * kap + dsk * bb;
    }
    {   // M[i][tau] = w*K[i-tau] (tau<=i), + dsk*w on diag
        int i = n;
        #pragma unroll
        for (int j = 0; j < 16; j++) {
            int tau = q * 16 + j;
            float val = (tau <= i) ? w * Ksm[i - tau] : 0.f;
            if (tau == i) val += dsk * w;
            g_M[d * 4096 + swzi(i, tau)] = __float2half_rn(val);
        }
    }
}

// ---------------- fused SSM + tail head ----------------
__global__ __launch_bounds__(256, 4)
void ssm_mma(const float* __restrict__ w_in, const float* __restrict__ b_in,
             const float* __restrict__ W_head, const float* __restrict__ b_head,
             float* __restrict__ out) {
    extern __shared__ char smem[];
    const uint32_t sb = smem_u32(smem);
    const int tid = threadIdx.x, wid = tid >> 5, lane = tid & 31;
    const int m = blockIdx.x, d = blockIdx.y;

    if (tid < 64) reinterpret_cast<float*>(smem + OFF_BETA)[tid] = g_beta[d * 64 + tid];

    {   // cp.async staging: X, P, Q
        const char* xp = (const char*)g_x + (size_t)m * 16384;
        #pragma unroll
        for (int k = 0; k < 4; k++) {
            int i = (tid + k * 256) * 16;
            CP16(sb + OFF_X + i, xp + i);
        }
        const char* pp = (const char*)g_P + d * 8192;
        const char* qp = (const char*)g_Q + d * 8192;
        #pragma unroll
        for (int k = 0; k < 2; k++) {
            int i = (tid + k * 256) * 16;
            CP16(sb + OFF_U + i, pp + i);
            CP16(sb + OFF_Q + i, qp + i);
        }
    }
    CP_COMMIT(); CP_WAIT0();
    __syncthreads();

    // MMA1: F = X . P^T
    float C1[8][4];
    #pragma unroll
    for (int i = 0; i < 8; i++)
        #pragma unroll
        for (int k = 0; k < 4; k++) C1[i][k] = 0.f;
    mm1(C1, sb + OFF_X, sb + OFF_U, lane, wid * 16);

    {   // store F as fp16 into SF region (swizzled 128B pitch)
        int rg = wid * 16 + (lane >> 2), cb = (lane & 3) * 2;
        uint32_t xr0 = (uint32_t)(rg & 7) << 4;
        #pragma unroll
        for (int nt = 0; nt < 8; nt++) {
            int col2 = (nt * 8 + cb) * 2;
            *reinterpret_cast<__half2*>(smem + OFF_SF + rg * 128 + (col2 ^ xr0)) =
                __floats2half2_rn(C1[nt][0], C1[nt][1]);
            *reinterpret_cast<__half2*>(smem + OFF_SF + (rg + 8) * 128 + (col2 ^ xr0)) =
                __floats2half2_rn(C1[nt][2], C1[nt][3]);
        }
    }
    __syncthreads();

    // warps 0-3: scan (read F elem, overwrite with seed) | warps 4-7: copy M over dead P
    if (wid < 4) {
        int bl = tid >> 6, n = tid & 63;
        float aLv = g_aL[d * 64 + n];
        float w = w_in[d];
        float bz = b_in[d] * g_zeta[d * 64 + n];
        float r = 0.f;
        #pragma unroll 8
        for (int c = 0; c < 64; c++) {
            int row = bl * 64 + c;
            __half* slot = reinterpret_cast<__half*>(
                smem + OFF_SF + row * 128 + ((n * 2) ^ ((c & 7) << 4)));
            float Fv = __half2float(*slot);       // read F first
            *slot = __float2half_rn(r);           // then overwrite with seed
            r = fmaf(aLv, r, fmaf(w, Fv, bz));
        }
    } else {
        const char* mp = (const char*)g_M + d * 8192;
        int t2 = tid - 128;
        #pragma unroll
        for (int k = 0; k < 4; k++) {
            int i = (t2 + k * 128) * 16;
            CP16(sb + OFF_U + i, mp + i);
        }
        CP_COMMIT(); CP_WAIT0();
    }
    __syncthreads();

    // MMA2: y = X.M'^T + S.Q^T ; epilogue gelu+pool
    float C2[8][4];
    #pragma unroll
    for (int i = 0; i < 8; i++)
        #pragma unroll
        for (int k = 0; k < 4; k++) C2[i][k] = 0.f;
    mm1(C2, sb + OFF_X, sb + OFF_U, lane, wid * 16);
    mm1(C2, sb + OFF_SF, sb + OFF_Q, lane, wid * 16);

    {
        const float* beta = reinterpret_cast<const float*>(smem + OFF_BETA);
        float ps = 0.f, pm = -3.402823466e38f;
        #pragma unroll
        for (int nt = 0; nt < 8; nt++) {
            float2 b2 = *reinterpret_cast<const float2*>(beta + nt * 8 + (lane & 3) * 2);
            #pragma unroll
            for (int k = 0; k < 4; k++) {
                float ypre = C2[nt][k] + ((k & 1) ? b2.y : b2.x);
                float inner = 0.7978845608028654f * ypre * fmaf(0.044715f, ypre * ypre, 1.0f);
                float th; asm("tanh.approx.f32 %0, %1;" : "=f"(th) : "f"(inner));
                float h = 0.5f * ypre * (1.0f + th);
                ps += h;
                pm = fmaxf(pm, h);
            }
        }
        #pragma unroll
        for (int o = 16; o > 0; o >>= 1) {
            ps += __shfl_xor_sync(0xffffffffu, ps, o);
            pm = fmaxf(pm, __shfl_xor_sync(0xffffffffu, pm, o));
        }
        float* wp = reinterpret_cast<float*>(smem + OFF_WP);
        if (lane == 0) { wp[wid * 2] = ps; wp[wid * 2 + 1] = pm; }
    }
    __syncthreads();
    if (tid < 2) {
        const float* wp = reinterpret_cast<const float*>(smem + OFF_WP);
        int w0 = tid * 4;
        float s = wp[(w0 + 0) * 2] + wp[(w0 + 1) * 2] + wp[(w0 + 2) * 2] + wp[(w0 + 3) * 2];
        float mx = fmaxf(fmaxf(wp[(w0 + 0) * 2 + 1], wp[(w0 + 1) * 2 + 1]),
                         fmaxf(wp[(w0 + 2) * 2 + 1], wp[(w0 + 3) * 2 + 1]));
        int b = m * 2 + tid;
        g_pool[(b * DM + d) * 2] = s;
        g_pool[(b * DM + d) * 2 + 1] = mx;
    }

    // ---- last-CTA head ----
    __shared__ unsigned int s_last;
    __threadfence();
    __syncthreads();
    if (tid == 0) {
        unsigned int v = atomicAdd(&g_ctr, 1u);
        s_last = (v == TOTAL_CTAS - 1) ? 1u : 0u;
    }
    __syncthreads();
    if (s_last) {
        __threadfence();   // acquire all pool writes
        // warp w handles batches w*4 .. w*4+3; lane covers 16 of 512 concat dims
        #pragma unroll
        for (int bb = 0; bb < 4; bb++) {
            int b = wid * 4 + bb;
            float acc[NCLS];
            #pragma unroll
            for (int k = 0; k < NCLS; k++) acc[k] = 0.f;
            #pragma unroll
            for (int j = 0; j < 16; j++) {
                int dd = lane + j * 32;          // 0..511
                float v;
                if (dd < DM) v = g_pool[(b * DM + dd) * 2] * (1.0f / (float)T_TOTAL);
                else         v = g_pool[(b * DM + (dd - DM)) * 2 + 1];
                #pragma unroll
                for (int k = 0; k < NCLS; k++)
                    acc[k] = fmaf(v, W_head[dd * NCLS + k], acc[k]);
            }
            #pragma unroll
            for (int k = 0; k < NCLS; k++) {
                float v = acc[k];
                #pragma unroll
                for (int o = 16; o > 0; o >>= 1) v += __shfl_xor_sync(0xffffffffu, v, o);
                if (lane == 0) out[b * NCLS + k] = v + b_head[k];
            }
        }
        __syncthreads();
        if (tid == 0) g_ctr = 0;   // reset for next graph replay
    }
}

extern "C" void kernel_launch(void* const* d_in, const int* in_sizes, int n_in,
                              void* d_out, int out_size) {
    const float* x      = (const float*)d_in[0];
    const float* w_in   = (const float*)d_in[1];
    const float* b_in   = (const float*)d_in[2];
    const float* A_diag = (const float*)d_in[3];
    const float* B_in   = (const float*)d_in[4];
    const float* C_out  = (const float*)d_in[5];
    const float* D_skip = (const float*)d_in[6];
    const float* W_head = (const float*)d_in[7];
    const float* b_head = (const float*)d_in[8];
    float* out = (float*)d_out;

    cudaFuncSetAttribute(ssm_mma, cudaFuncAttributeMaxDynamicSharedMemorySize, SMEM_BYTES);
    prep<<<384, 256>>>(x, w_in, b_in, A_diag, B_in, C_out, D_skip);
    ssm_mma<<<dim3(MT, DM), 256, SMEM_BYTES>>>(w_in, b_in, W_head, b_head, out);
}

// round 9
// speedup vs baseline: 1.0880x; 1.0880x over previous
#include <cuda_runtime.h>
#include <cuda_fp16.h>
#include <cstdint>

#define BATCH 32
#define T_TOTAL 4096
#define DM 256
#define SN 64
#define NCLS 5
#define L 64
#define MT2 32                 /* one batch per CTA */
#define TOTAL_CTAS (MT2 * DM)  /* 8192 */

// ---- gmem precomputed operands (pre-swizzled fp16) ----
__device__ __half g_x[BATCH * T_TOTAL];
__device__ __half g_P[DM * 4096];
__device__ __half g_M[DM * 4096];
__device__ __half g_Q[DM * 4096];
__device__ float g_beta[DM * L], g_zeta[DM * SN], g_aL[DM * SN];
__device__ float g_pool[BATCH * DM * 2];
__device__ unsigned int g_ctr = 0;

// ---- smem layout (bytes) ----
#define OFF_BETA 0
#define OFF_WP   256
#define OFF_X    512               /* 64 x 128B fp16 */
#define OFF_SF   8704              /* F (MMA1 out) then S (seeds): 64 x 128B */
#define OFF_U    16896             /* P then M: 64 x 128B */
#define OFF_Q    25088             /* 64 x 128B */
#define SMEM_BYTES 33280

__device__ __forceinline__ uint32_t smem_u32(const void* p) {
    uint32_t a;
    asm("{ .reg .u64 t; cvta.to.shared.u64 t, %1; cvt.u32.u64 %0, t; }" : "=r"(a) : "l"(p));
    return a;
}
#define CP16(dst, src) asm volatile("cp.async.cg.shared.global [%0], [%1], 16;" :: "r"(dst), "l"(src))
#define CP_COMMIT()    asm volatile("cp.async.commit_group;" ::: "memory")
#define CP_WAIT0()     asm volatile("cp.async.wait_group 0;" ::: "memory")

__device__ __forceinline__ void ldsm4(uint32_t addr, uint32_t r[4]) {
    asm volatile("ldmatrix.sync.aligned.m8n8.x4.shared.b16 {%0,%1,%2,%3}, [%4];"
                 : "=r"(r[0]), "=r"(r[1]), "=r"(r[2]), "=r"(r[3]) : "r"(addr));
}
__device__ __forceinline__ void mma_f16(float c[4], const uint32_t a[4], uint32_t b0, uint32_t b1) {
    asm volatile("mma.sync.aligned.m16n8k16.row.col.f32.f16.f16.f32 "
                 "{%0,%1,%2,%3}, {%4,%5,%6,%7}, {%8,%9}, {%0,%1,%2,%3};"
                 : "+f"(c[0]), "+f"(c[1]), "+f"(c[2]), "+f"(c[3])
                 : "r"(a[0]), "r"(a[1]), "r"(a[2]), "r"(a[3]), "r"(b0), "r"(b1));
}
// swizzled elem index within a 128B-row fp16 tile
__device__ __forceinline__ int swzi(int row, int col) {
    return ((row * 128 + col * 2) ^ ((row & 7) << 4)) >> 1;
}

// single-product fp16 matmul-accumulate: C[16 x 64] += A(16xK64) * B(64xK64)^T
__device__ __forceinline__ void mm1(float C[8][4], uint32_t aBase, uint32_t bBase,
                                    int lane, int row0) {
    const int arow = row0 + (lane & 15);
    const uint32_t abase = (uint32_t)arow * 128;
    const uint32_t axor = (uint32_t)(arow & 7) << 4;
    const uint32_t ak16 = ((lane >> 4) & 1) * 16;
    const int brow = ((lane >> 3) & 2) * 4 + (lane & 7);
    const uint32_t bxor = (uint32_t)(brow & 7) << 4;
    const uint32_t bk16 = ((lane >> 3) & 1) * 16;
    #pragma unroll
    for (int kc = 0; kc < 4; kc++) {
        uint32_t a[4];
        ldsm4(aBase + abase + ((ak16 + kc * 32) ^ axor), a);
        #pragma unroll
        for (int j = 0; j < 4; j++) {
            uint32_t boff = (uint32_t)(j * 16 + brow) * 128 + ((bk16 + kc * 32) ^ bxor);
            uint32_t b[4];
            ldsm4(bBase + boff, b);
            mma_f16(C[2 * j],     a, b[0], b[1]);
            mma_f16(C[2 * j + 1], a, b[2], b[3]);
        }
    }
}

// ---------------- merged prep: x->fp16 swizzle (blocks 0-127) + per-d tiles (128-383) ----------------
__global__ void prep(const float* __restrict__ x,
                     const float* __restrict__ w_in, const float* __restrict__ b_in,
                     const float* __restrict__ A_diag, const float* __restrict__ B_in,
                     const float* __restrict__ C_out, const float* __restrict__ D_skip) {
    const int tid = threadIdx.x;
    if (blockIdx.x < 128) {
        int e = (blockIdx.x * 256 + tid) * 4;
        float4 v = *reinterpret_cast<const float4*>(x + e);
        int b = e >> 12, t = e & 4095;
        int rg = b * 64 + (t >> 6), col = t & 63;
        int boff = rg * 128 + ((col * 2) ^ ((rg & 7) << 4));
        __half2 p0 = __floats2half2_rn(v.x, v.y);
        __half2 p1 = __floats2half2_rn(v.z, v.w);
        char* p = (char*)g_x + boff;
        *(__half2*)p = p0;
        *(__half2*)(p + 4) = p1;
        return;
    }
    const int d = blockIdx.x - 128;
    const int n = tid & 63, q = tid >> 6;
    __shared__ float gmat[64][65];
    __shared__ float Kp[64][4];
    __shared__ float Ksm[64];
    __shared__ float zp[4][64];

    float a = A_diag[d * 64 + n];
    float g = B_in[d * 64 + n] * C_out[d * 64 + n];
    float a2 = a * a, a4 = a2 * a2, a8 = a4 * a4, a16 = a8 * a8;
    float a32 = a16 * a16, a48 = a32 * a16, a64v = a32 * a32;
    float s = (q == 0) ? 1.f : ((q == 1) ? a16 : ((q == 2) ? a32 : a48));

    {   // P[n][tau] = a^(63-tau); zeta partial
        float p = s, zs = 0.f;
        #pragma unroll
        for (int j = 0; j < 16; j++) {
            int e = q * 16 + j, tau = 63 - e;
            g_P[d * 4096 + swzi(n, tau)] = __float2half_rn(p);
            zs += p; p *= a;
        }
        zp[q][n] = zs;
    }
    {   // Q[i][n] = g*a^(i+1)
        float t = g * s * a;
        #pragma unroll
        for (int j = 0; j < 16; j++) {
            int i = q * 16 + j;
            g_Q[d * 4096 + swzi(i, n)] = __float2half_rn(t);
            t *= a;
        }
    }
    {   // gmat[delta][n] = g*a^delta
        float u = g * s;
        #pragma unroll
        for (int j = 0; j < 16; j++) { gmat[q * 16 + j][n] = u; u *= a; }
    }
    __syncthreads();
    if (q == 0) {
        g_zeta[d * 64 + n] = zp[0][n] + zp[1][n] + zp[2][n] + zp[3][n];
        g_aL[d * 64 + n] = a64v;
    }
    {   // K[delta] partial over n
        float ss = 0.f;
        #pragma unroll
        for (int j = 0; j < 16; j++) ss += gmat[n][q * 16 + j];
        Kp[n][q] = ss;
    }
    __syncthreads();
    if (tid < 64) Ksm[tid] = Kp[tid][0] + Kp[tid][1] + Kp[tid][2] + Kp[tid][3];
    __syncthreads();
    float w = w_in[d], bb = b_in[d], dsk = D_skip[d];
    if (tid < 64) {
        float kap = 0.f;
        for (int dd = 0; dd <= tid; dd++) kap += Ksm[dd];
        g_beta[d * 64 + tid] = bb * kap + dsk * bb;
    }
    {   // M[i][tau] = w*K[i-tau] (tau<=i), + dsk*w on diag
        int i = n;
        #pragma unroll
        for (int j = 0; j < 16; j++) {
            int tau = q * 16 + j;
            float val = (tau <= i) ? w * Ksm[i - tau] : 0.f;
            if (tau == i) val += dsk * w;
            g_M[d * 4096 + swzi(i, tau)] = __float2half_rn(val);
        }
    }
}

// ---------------- fused SSM (128 thr, one batch x one d per CTA) + tail head ----------------
__global__ __launch_bounds__(128, 6)
void ssm_mma(const float* __restrict__ w_in, const float* __restrict__ b_in,
             const float* __restrict__ W_head, const float* __restrict__ b_head,
             float* __restrict__ out) {
    extern __shared__ char smem[];
    const uint32_t sb = smem_u32(smem);
    const int tid = threadIdx.x, wid = tid >> 5, lane = tid & 31;
    const int m = blockIdx.x, d = blockIdx.y;   // m = batch

    if (tid < 64) reinterpret_cast<float*>(smem + OFF_BETA)[tid] = g_beta[d * 64 + tid];

    {   // cp.async staging: X (8KB), P (8KB), Q (8KB)
        const char* xp = (const char*)g_x + (size_t)m * 8192;
        const char* pp = (const char*)g_P + d * 8192;
        const char* qp = (const char*)g_Q + d * 8192;
        #pragma unroll
        for (int k = 0; k < 4; k++) {
            int i = (tid + k * 128) * 16;
            CP16(sb + OFF_X + i, xp + i);
            CP16(sb + OFF_U + i, pp + i);
            CP16(sb + OFF_Q + i, qp + i);
        }
    }
    CP_COMMIT(); CP_WAIT0();
    __syncthreads();

    // MMA1: F = X . P^T   (each warp: 16 rows)
    float C1[8][4];
    #pragma unroll
    for (int i = 0; i < 8; i++)
        #pragma unroll
        for (int k = 0; k < 4; k++) C1[i][k] = 0.f;
    mm1(C1, sb + OFF_X, sb + OFF_U, lane, wid * 16);

    {   // store F as fp16 into SF region (swizzled 128B pitch)
        int rg = wid * 16 + (lane >> 2), cb = (lane & 3) * 2;
        uint32_t xr0 = (uint32_t)(rg & 7) << 4;
        #pragma unroll
        for (int nt = 0; nt < 8; nt++) {
            int col2 = (nt * 8 + cb) * 2;
            *reinterpret_cast<__half2*>(smem + OFF_SF + rg * 128 + (col2 ^ xr0)) =
                __floats2half2_rn(C1[nt][0], C1[nt][1]);
            *reinterpret_cast<__half2*>(smem + OFF_SF + (rg + 8) * 128 + (col2 ^ xr0)) =
                __floats2half2_rn(C1[nt][2], C1[nt][3]);
        }
    }
    __syncthreads();

    // warps 0-1: scan (read F, overwrite with seed) | warps 2-3: copy M over dead P
    if (tid < 64) {
        int n = tid;
        float aLv = g_aL[d * 64 + n];
        float w = w_in[d];
        float bz = b_in[d] * g_zeta[d * 64 + n];
        float r = 0.f;
        #pragma unroll 8
        for (int c = 0; c < 64; c++) {
            __half* slot = reinterpret_cast<__half*>(
                smem + OFF_SF + c * 128 + ((n * 2) ^ ((c & 7) << 4)));
            float Fv = __half2float(*slot);       // read F first
            *slot = __float2half_rn(r);           // then overwrite with seed
            r = fmaf(aLv, r, fmaf(w, Fv, bz));
        }
    } else {
        const char* mp = (const char*)g_M + d * 8192;
        int t2 = tid - 64;
        #pragma unroll
        for (int k = 0; k < 8; k++) {
            int i = (t2 + k * 64) * 16;
            CP16(sb + OFF_U + i, mp + i);
        }
        CP_COMMIT(); CP_WAIT0();
    }
    __syncthreads();

    // MMA2: y = X.M'^T + S.Q^T ; epilogue gelu+pool
    float C2[8][4];
    #pragma unroll
    for (int i = 0; i < 8; i++)
        #pragma unroll
        for (int k = 0; k < 4; k++) C2[i][k] = 0.f;
    mm1(C2, sb + OFF_X, sb + OFF_U, lane, wid * 16);
    mm1(C2, sb + OFF_SF, sb + OFF_Q, lane, wid * 16);

    {
        const float* beta = reinterpret_cast<const float*>(smem + OFF_BETA);
        float ps = 0.f, pm = -3.402823466e38f;
        #pragma unroll
        for (int nt = 0; nt < 8; nt++) {
            float2 b2 = *reinterpret_cast<const float2*>(beta + nt * 8 + (lane & 3) * 2);
            #pragma unroll
            for (int k = 0; k < 4; k++) {
                float ypre = C2[nt][k] + ((k & 1) ? b2.y : b2.x);
                float inner = 0.7978845608028654f * ypre * fmaf(0.044715f, ypre * ypre, 1.0f);
                float th; asm("tanh.approx.f32 %0, %1;" : "=f"(th) : "f"(inner));
                float h = 0.5f * ypre * (1.0f + th);
                ps += h;
                pm = fmaxf(pm, h);
            }
        }
        #pragma unroll
        for (int o = 16; o > 0; o >>= 1) {
            ps += __shfl_xor_sync(0xffffffffu, ps, o);
            pm = fmaxf(pm, __shfl_xor_sync(0xffffffffu, pm, o));
        }
        float* wp = reinterpret_cast<float*>(smem + OFF_WP);
        if (lane == 0) { wp[wid * 2] = ps; wp[wid * 2 + 1] = pm; }
    }
    __syncthreads();
    if (tid == 0) {
        const float* wp = reinterpret_cast<const float*>(smem + OFF_WP);
        float s = wp[0] + wp[2] + wp[4] + wp[6];
        float mx = fmaxf(fmaxf(wp[1], wp[3]), fmaxf(wp[5], wp[7]));
        g_pool[(m * DM + d) * 2] = s;
        g_pool[(m * DM + d) * 2 + 1] = mx;
    }

    // ---- last-CTA head ----
    __shared__ unsigned int s_last;
    __threadfence();
    __syncthreads();
    if (tid == 0) {
        unsigned int v = atomicAdd(&g_ctr, 1u);
        s_last = (v == TOTAL_CTAS - 1) ? 1u : 0u;
    }
    __syncthreads();
    if (s_last) {
        __threadfence();   // acquire all pool writes
        // 4 warps; warp w handles batches w*8 .. w*8+7
        #pragma unroll
        for (int bb = 0; bb < 8; bb++) {
            int b = wid * 8 + bb;
            float acc[NCLS];
            #pragma unroll
            for (int k = 0; k < NCLS; k++) acc[k] = 0.f;
            #pragma unroll
            for (int j = 0; j < 16; j++) {
                int dd = lane + j * 32;          // 0..511
                float v;
                if (dd < DM) v = g_pool[(b * DM + dd) * 2] * (1.0f / (float)T_TOTAL);
                else         v = g_pool[(b * DM + (dd - DM)) * 2 + 1];
                #pragma unroll
                for (int k = 0; k < NCLS; k++)
                    acc[k] = fmaf(v, W_head[dd * NCLS + k], acc[k]);
            }
            #pragma unroll
            for (int k = 0; k < NCLS; k++) {
                float v = acc[k];
                #pragma unroll
                for (int o = 16; o > 0; o >>= 1) v += __shfl_xor_sync(0xffffffffu, v, o);
                if (lane == 0) out[b * NCLS + k] = v + b_head[k];
            }
        }
        __syncthreads();
        if (tid == 0) g_ctr = 0;   // reset for next graph replay
    }
}

extern "C" void kernel_launch(void* const* d_in, const int* in_sizes, int n_in,
                              void* d_out, int out_size) {
    const float* x      = (const float*)d_in[0];
    const float* w_in   = (const float*)d_in[1];
    const float* b_in   = (const float*)d_in[2];
    const float* A_diag = (const float*)d_in[3];
    const float* B_in   = (const float*)d_in[4];
    const float* C_out  = (const float*)d_in[5];
    const float* D_skip = (const float*)d_in[6];
    const float* W_head = (const float*)d_in[7];
    const float* b_head = (const float*)d_in[8];
    float* out = (float*)d_out;

    cudaFuncSetAttribute(ssm_mma, cudaFuncAttributeMaxDynamicSharedMemorySize, SMEM_BYTES);
    prep<<<384, 256>>>(x, w_in, b_in, A_diag, B_in, C_out, D_skip);
    ssm_mma<<<dim3(MT2, DM), 128, SMEM_BYTES>>>(w_in, b_in, W_head, b_head, out);
}

// round 10
// speedup vs baseline: 1.1540x; 1.0606x over previous
#include <cuda_runtime.h>
#include <cuda_fp16.h>
#include <cstdint>

#define BATCH 32
#define T_TOTAL 4096
#define DM 256
#define SN 64
#define NCLS 5
#define L 64
#define MT 16                  /* 128-row tiles: 2 batches per CTA */
#define TOTAL_CTAS (MT * DM)   /* 4096 */

// ---- gmem precomputed operands (pre-swizzled fp16) ----
__device__ __half g_x[BATCH * T_TOTAL];
__device__ __half g_P[DM * 4096];
__device__ __half g_M[DM * 4096];
__device__ __half g_Q[DM * 4096];
__device__ float g_beta[DM * L], g_zeta[DM * SN], g_aL[DM * SN];
__device__ float g_pool[BATCH * DM * 2];
__device__ unsigned int g_ctr = 0;

// ---- smem layout (bytes) ----
#define OFF_BETA 0                 /* 64 f32 */
#define OFF_WP   256               /* 16 f32 */
#define OFF_BZ   320               /* 64 f32: b*zeta[n] */
#define OFF_X    640               /* 128 x 128B fp16 */
#define OFF_SF   17024             /* f (MMA1 out, pre-scanned) then seeds: 128 x 128B */
#define OFF_P    33408             /* 64 x 128B */
#define OFF_M    41600             /* 64 x 128B */
#define OFF_Q    49792             /* 64 x 128B */
#define SMEM_BYTES 57984

__device__ __forceinline__ uint32_t smem_u32(const void* p) {
    uint32_t a;
    asm("{ .reg .u64 t; cvta.to.shared.u64 t, %1; cvt.u32.u64 %0, t; }" : "=r"(a) : "l"(p));
    return a;
}
#define CP16(dst, src) asm volatile("cp.async.cg.shared.global [%0], [%1], 16;" :: "r"(dst), "l"(src))
#define CP_COMMIT()    asm volatile("cp.async.commit_group;" ::: "memory")
#define CP_WAIT0()     asm volatile("cp.async.wait_group 0;" ::: "memory")

__device__ __forceinline__ void ldsm4(uint32_t addr, uint32_t r[4]) {
    asm volatile("ldmatrix.sync.aligned.m8n8.x4.shared.b16 {%0,%1,%2,%3}, [%4];"
                 : "=r"(r[0]), "=r"(r[1]), "=r"(r[2]), "=r"(r[3]) : "r"(addr));
}
__device__ __forceinline__ void mma_f16(float c[4], const uint32_t a[4], uint32_t b0, uint32_t b1) {
    asm volatile("mma.sync.aligned.m16n8k16.row.col.f32.f16.f16.f32 "
                 "{%0,%1,%2,%3}, {%4,%5,%6,%7}, {%8,%9}, {%0,%1,%2,%3};"
                 : "+f"(c[0]), "+f"(c[1]), "+f"(c[2]), "+f"(c[3])
                 : "r"(a[0]), "r"(a[1]), "r"(a[2]), "r"(a[3]), "r"(b0), "r"(b1));
}
// swizzled elem index within a 128B-row fp16 tile
__device__ __forceinline__ int swzi(int row, int col) {
    return ((row * 128 + col * 2) ^ ((row & 7) << 4)) >> 1;
}

// single-product fp16 matmul-accumulate: C[16 x 64] += A(16xK64) * B(64xK64)^T
__device__ __forceinline__ void mm1(float C[8][4], uint32_t aBase, uint32_t bBase,
                                    int lane, int row0) {
    const int arow = row0 + (lane & 15);
    const uint32_t abase = (uint32_t)arow * 128;
    const uint32_t axor = (uint32_t)(arow & 7) << 4;
    const uint32_t ak16 = ((lane >> 4) & 1) * 16;
    const int brow = ((lane >> 3) & 2) * 4 + (lane & 7);
    const uint32_t bxor = (uint32_t)(brow & 7) << 4;
    const uint32_t bk16 = ((lane >> 3) & 1) * 16;
    #pragma unroll
    for (int kc = 0; kc < 4; kc++) {
        uint32_t a[4];
        ldsm4(aBase + abase + ((ak16 + kc * 32) ^ axor), a);
        #pragma unroll
        for (int j = 0; j < 4; j++) {
            uint32_t boff = (uint32_t)(j * 16 + brow) * 128 + ((bk16 + kc * 32) ^ bxor);
            uint32_t b[4];
            ldsm4(bBase + boff, b);
            mma_f16(C[2 * j],     a, b[0], b[1]);
            mma_f16(C[2 * j + 1], a, b[2], b[3]);
        }
    }
}

// ---------------- merged prep: x->fp16 swizzle (blocks 0-127) + per-d tiles (128-383) ----------------
__global__ void prep(const float* __restrict__ x,
                     const float* __restrict__ w_in, const float* __restrict__ b_in,
                     const float* __restrict__ A_diag, const float* __restrict__ B_in,
                     const float* __restrict__ C_out, const float* __restrict__ D_skip) {
    const int tid = threadIdx.x;
    if (blockIdx.x < 128) {
        int e = (blockIdx.x * 256 + tid) * 4;
        float4 v = *reinterpret_cast<const float4*>(x + e);
        int b = e >> 12, t = e & 4095;
        int rg = b * 64 + (t >> 6), col = t & 63;
        int boff = rg * 128 + ((col * 2) ^ ((rg & 7) << 4));
        __half2 p0 = __floats2half2_rn(v.x, v.y);
        __half2 p1 = __floats2half2_rn(v.z, v.w);
        char* p = (char*)g_x + boff;
        *(__half2*)p = p0;
        *(__half2*)(p + 4) = p1;
        return;
    }
    const int d = blockIdx.x - 128;
    const int n = tid & 63, q = tid >> 6;
    __shared__ float gmat[64][65];
    __shared__ float Kp[64][4];
    __shared__ float Ksm[64];
    __shared__ float zp[4][64];

    float a = A_diag[d * 64 + n];
    float g = B_in[d * 64 + n] * C_out[d * 64 + n];
    float a2 = a * a, a4 = a2 * a2, a8 = a4 * a4, a16 = a8 * a8;
    float a32 = a16 * a16, a48 = a32 * a16, a64v = a32 * a32;
    float s = (q == 0) ? 1.f : ((q == 1) ? a16 : ((q == 2) ? a32 : a48));

    {   // P[n][tau] = a^(63-tau); zeta partial
        float p = s, zs = 0.f;
        #pragma unroll
        for (int j = 0; j < 16; j++) {
            int e = q * 16 + j, tau = 63 - e;
            g_P[d * 4096 + swzi(n, tau)] = __float2half_rn(p);
            zs += p; p *= a;
        }
        zp[q][n] = zs;
    }
    {   // Q[i][n] = g*a^(i+1)
        float t = g * s * a;
        #pragma unroll
        for (int j = 0; j < 16; j++) {
            int i = q * 16 + j;
            g_Q[d * 4096 + swzi(i, n)] = __float2half_rn(t);
            t *= a;
        }
    }
    {   // gmat[delta][n] = g*a^delta
        float u = g * s;
        #pragma unroll
        for (int j = 0; j < 16; j++) { gmat[q * 16 + j][n] = u; u *= a; }
    }
    __syncthreads();
    if (q == 0) {
        g_zeta[d * 64 + n] = zp[0][n] + zp[1][n] + zp[2][n] + zp[3][n];
        g_aL[d * 64 + n] = a64v;
    }
    {   // K[delta] partial over n
        float ss = 0.f;
        #pragma unroll
        for (int j = 0; j < 16; j++) ss += gmat[n][q * 16 + j];
        Kp[n][q] = ss;
    }
    __syncthreads();
    if (tid < 64) Ksm[tid] = Kp[tid][0] + Kp[tid][1] + Kp[tid][2] + Kp[tid][3];
    __syncthreads();
    float w = w_in[d], bb = b_in[d], dsk = D_skip[d];
    if (tid < 64) {
        float kap = 0.f;
        for (int dd = 0; dd <= tid; dd++) kap += Ksm[dd];
        g_beta[d * 64 + tid] = bb * kap + dsk * bb;
    }
    {   // M[i][tau] = w*K[i-tau] (tau<=i), + dsk*w on diag
        int i = n;
        #pragma unroll
        for (int j = 0; j < 16; j++) {
            int tau = q * 16 + j;
            float val = (tau <= i) ? w * Ksm[i - tau] : 0.f;
            if (tau == i) val += dsk * w;
            g_M[d * 4096 + swzi(i, tau)] = __float2half_rn(val);
        }
    }
}

// ---------------- fused SSM (256 thr, 2 batches x 1 d per CTA) + tail head ----------------
__global__ __launch_bounds__(256, 3)
void ssm_mma(const float* __restrict__ w_in, const float* __restrict__ b_in,
             const float* __restrict__ W_head, const float* __restrict__ b_head,
             float* __restrict__ out) {
    extern __shared__ char smem[];
    const uint32_t sb = smem_u32(smem);
    const int tid = threadIdx.x, wid = tid >> 5, lane = tid & 31;
    const int m = blockIdx.x, d = blockIdx.y;
    const float w = w_in[d];

    if (tid < 64) {
        reinterpret_cast<float*>(smem + OFF_BETA)[tid] = g_beta[d * 64 + tid];
        reinterpret_cast<float*>(smem + OFF_BZ)[tid] = b_in[d] * g_zeta[d * 64 + tid];
    }

    {   // cp.async staging: X (16KB), P, M, Q (8KB each) — all upfront
        const char* xp = (const char*)g_x + (size_t)m * 16384;
        #pragma unroll
        for (int k = 0; k < 4; k++) {
            int i = (tid + k * 256) * 16;
            CP16(sb + OFF_X + i, xp + i);
        }
        const char* pp = (const char*)g_P + d * 8192;
        const char* mp = (const char*)g_M + d * 8192;
        const char* qp = (const char*)g_Q + d * 8192;
        #pragma unroll
        for (int k = 0; k < 2; k++) {
            int i = (tid + k * 256) * 16;
            CP16(sb + OFF_P + i, pp + i);
            CP16(sb + OFF_M + i, mp + i);
            CP16(sb + OFF_Q + i, qp + i);
        }
    }
    CP_COMMIT(); CP_WAIT0();
    __syncthreads();

    // MMA1: F = X . P^T  (each warp: 16 rows)
    float C1[8][4];
    #pragma unroll
    for (int i = 0; i < 8; i++)
        #pragma unroll
        for (int k = 0; k < 4; k++) C1[i][k] = 0.f;
    mm1(C1, sb + OFF_X, sb + OFF_P, lane, wid * 16);

    {   // store f = w*F + bz[n] directly as fp16 into SF (swizzled 128B pitch)
        const float* bz = reinterpret_cast<const float*>(smem + OFF_BZ);
        int rg = wid * 16 + (lane >> 2), cb = (lane & 3) * 2;
        uint32_t xr0 = (uint32_t)(rg & 7) << 4;
        #pragma unroll
        for (int nt = 0; nt < 8; nt++) {
            float2 bz2 = *reinterpret_cast<const float2*>(bz + nt * 8 + cb);
            int col2 = (nt * 8 + cb) * 2;
            *reinterpret_cast<__half2*>(smem + OFF_SF + rg * 128 + (col2 ^ xr0)) =
                __floats2half2_rn(fmaf(w, C1[nt][0], bz2.x), fmaf(w, C1[nt][1], bz2.y));
            *reinterpret_cast<__half2*>(smem + OFF_SF + (rg + 8) * 128 + (col2 ^ xr0)) =
                __floats2half2_rn(fmaf(w, C1[nt][2], bz2.x), fmaf(w, C1[nt][3], bz2.y));
        }
    }
    __syncthreads();

    // scan (tid<128): single-FMA chain; read f, overwrite with seed
    if (tid < 128) {
        int bl = tid >> 6, n = tid & 63;
        float aLv = g_aL[d * 64 + n];
        float r = 0.f;
        #pragma unroll 8
        for (int c = 0; c < 64; c++) {
            __half* slot = reinterpret_cast<__half*>(
                smem + OFF_SF + (bl * 64 + c) * 128 + ((n * 2) ^ ((c & 7) << 4)));
            float fv = __half2float(*slot);       // read f first
            *slot = __float2half_rn(r);           // then overwrite with seed
            r = fmaf(aLv, r, fv);
        }
    }
    __syncthreads();

    // MMA2: y = X.M'^T + S.Q^T ; epilogue gelu+pool
    float C2[8][4];
    #pragma unroll
    for (int i = 0; i < 8; i++)
        #pragma unroll
        for (int k = 0; k < 4; k++) C2[i][k] = 0.f;
    mm1(C2, sb + OFF_X, sb + OFF_M, lane, wid * 16);
    mm1(C2, sb + OFF_SF, sb + OFF_Q, lane, wid * 16);

    {
        const float* beta = reinterpret_cast<const float*>(smem + OFF_BETA);
        float ps = 0.f, pm = -3.402823466e38f;
        #pragma unroll
        for (int nt = 0; nt < 8; nt++) {
            float2 b2 = *reinterpret_cast<const float2*>(beta + nt * 8 + (lane & 3) * 2);
            #pragma unroll
            for (int k = 0; k < 4; k++) {
                float ypre = C2[nt][k] + ((k & 1) ? b2.y : b2.x);
                float inner = 0.7978845608028654f * ypre * fmaf(0.044715f, ypre * ypre, 1.0f);
                float th; asm("tanh.approx.f32 %0, %1;" : "=f"(th) : "f"(inner));
                float h = 0.5f * ypre * (1.0f + th);
                ps += h;
                pm = fmaxf(pm, h);
            }
        }
        #pragma unroll
        for (int o = 16; o > 0; o >>= 1) {
            ps += __shfl_xor_sync(0xffffffffu, ps, o);
            pm = fmaxf(pm, __shfl_xor_sync(0xffffffffu, pm, o));
        }
        float* wp = reinterpret_cast<float*>(smem + OFF_WP);
        if (lane == 0) { wp[wid * 2] = ps; wp[wid * 2 + 1] = pm; }
    }
    __syncthreads();
    if (tid < 2) {
        // warps 0-3 -> batch m*2, warps 4-7 -> batch m*2+1
        const float* wp = reinterpret_cast<const float*>(smem + OFF_WP);
        int w0 = tid * 4;
        float s = wp[(w0 + 0) * 2] + wp[(w0 + 1) * 2] + wp[(w0 + 2) * 2] + wp[(w0 + 3) * 2];
        float mx = fmaxf(fmaxf(wp[(w0 + 0) * 2 + 1], wp[(w0 + 1) * 2 + 1]),
                         fmaxf(wp[(w0 + 2) * 2 + 1], wp[(w0 + 3) * 2 + 1]));
        int b = m * 2 + tid;
        g_pool[(b * DM + d) * 2] = s;
        g_pool[(b * DM + d) * 2 + 1] = mx;
    }

    // ---- last-CTA head ----
    __shared__ unsigned int s_last;
    __threadfence();
    __syncthreads();
    if (tid == 0) {
        unsigned int v = atomicAdd(&g_ctr, 1u);
        s_last = (v == TOTAL_CTAS - 1) ? 1u : 0u;
    }
    __syncthreads();
    if (s_last) {
        __threadfence();   // acquire all pool writes
        // 8 warps; warp w handles batches w*4 .. w*4+3
        #pragma unroll
        for (int bb = 0; bb < 4; bb++) {
            int b = wid * 4 + bb;
            float acc[NCLS];
            #pragma unroll
            for (int k = 0; k < NCLS; k++) acc[k] = 0.f;
            #pragma unroll
            for (int j = 0; j < 16; j++) {
                int dd = lane + j * 32;          // 0..511
                float v;
                if (dd < DM) v = g_pool[(b * DM + dd) * 2] * (1.0f / (float)T_TOTAL);
                else         v = g_pool[(b * DM + (dd - DM)) * 2 + 1];
                #pragma unroll
                for (int k = 0; k < NCLS; k++)
                    acc[k] = fmaf(v, W_head[dd * NCLS + k], acc[k]);
            }
            #pragma unroll
            for (int k = 0; k < NCLS; k++) {
                float v = acc[k];
                #pragma unroll
                for (int o = 16; o > 0; o >>= 1) v += __shfl_xor_sync(0xffffffffu, v, o);
                if (lane == 0) out[b * NCLS + k] = v + b_head[k];
            }
        }
        __syncthreads();
        if (tid == 0) g_ctr = 0;   // reset for next graph replay
    }
}

extern "C" void kernel_launch(void* const* d_in, const int* in_sizes, int n_in,
                              void* d_out, int out_size) {
    const float* x      = (const float*)d_in[0];
    const float* w_in   = (const float*)d_in[1];
    const float* b_in   = (const float*)d_in[2];
    const float* A_diag = (const float*)d_in[3];
    const float* B_in   = (const float*)d_in[4];
    const float* C_out  = (const float*)d_in[5];
    const float* D_skip = (const float*)d_in[6];
    const float* W_head = (const float*)d_in[7];
    const float* b_head = (const float*)d_in[8];
    float* out = (float*)d_out;

    cudaFuncSetAttribute(ssm_mma, cudaFuncAttributeMaxDynamicSharedMemorySize, SMEM_BYTES);
    prep<<<384, 256>>>(x, w_in, b_in, A_diag, B_in, C_out, D_skip);
    ssm_mma<<<dim3(MT, DM), 256, SMEM_BYTES>>>(w_in, b_in, W_head, b_head, out);
}

// round 12
// speedup vs baseline: 1.3164x; 1.1408x over previous
#include <cuda_runtime.h>
#include <cuda_fp16.h>
#include <cstdint>

#define BATCH 32
#define T_TOTAL 4096
#define DM 256
#define SN 64
#define NCLS 5
#define L 64
#define MT 16                  /* 128-row tiles: 2 batches per CTA */
#define TOTAL_CTAS (MT * DM)   /* 4096 */

// ---- gmem precomputed operands (pre-swizzled fp16) ----
__device__ __half g_x[BATCH * T_TOTAL];
__device__ __half g_P[DM * 4096];
__device__ __half g_M[DM * 4096];
__device__ __half g_Q[DM * 4096];
__device__ float g_beta[DM * L], g_zeta[DM * SN], g_aL[DM * SN];
__device__ float g_pool[BATCH * DM * 2];
__device__ unsigned int g_ctr = 0;

// ---- smem layout (bytes) ----
#define OFF_BETA 0                 /* 64 f32 */
#define OFF_WP   256               /* 16 f32 */
#define OFF_BZ   320               /* 64 f32: b*zeta[n] */
#define OFF_X    640               /* 128 x 128B fp16 */
#define OFF_SF   17024             /* f (MMA1 out) then seeds: 128 x 128B */
#define OFF_P    33408             /* 64 x 128B */
#define OFF_M    41600             /* 64 x 128B */
#define OFF_Q    49792             /* 64 x 128B */
#define SMEM_BYTES 57984

__device__ __forceinline__ uint32_t smem_u32(const void* p) {
    uint32_t a;
    asm("{ .reg .u64 t; cvta.to.shared.u64 t, %1; cvt.u32.u64 %0, t; }" : "=r"(a) : "l"(p));
    return a;
}
#define CP16(dst, src) asm volatile("cp.async.cg.shared.global [%0], [%1], 16;" :: "r"(dst), "l"(src))
#define CP_COMMIT()    asm volatile("cp.async.commit_group;" ::: "memory")
#define CP_WAIT(n)     asm volatile("cp.async.wait_group %0;" :: "n"(n) : "memory")

__device__ __forceinline__ void ldsm4(uint32_t addr, uint32_t r[4]) {
    asm volatile("ldmatrix.sync.aligned.m8n8.x4.shared.b16 {%0,%1,%2,%3}, [%4];"
                 : "=r"(r[0]), "=r"(r[1]), "=r"(r[2]), "=r"(r[3]) : "r"(addr));
}
__device__ __forceinline__ void mma_f16(float c[4], const uint32_t a[4], uint32_t b0, uint32_t b1) {
    asm volatile("mma.sync.aligned.m16n8k16.row.col.f32.f16.f16.f32 "
                 "{%0,%1,%2,%3}, {%4,%5,%6,%7}, {%8,%9}, {%0,%1,%2,%3};"
                 : "+f"(c[0]), "+f"(c[1]), "+f"(c[2]), "+f"(c[3])
                 : "r"(a[0]), "r"(a[1]), "r"(a[2]), "r"(a[3]), "r"(b0), "r"(b1));
}
// swizzled elem index within a 128B-row fp16 tile
__device__ __forceinline__ int swzi(int row, int col) {
    return ((row * 128 + col * 2) ^ ((row & 7) << 4)) >> 1;
}

// 32x32 warp-tile fp16 matmul-accumulate over K=64:
// C covers rows [row0,row0+32) x cols [col0,col0+32). triM: skip tiles with tau>i (M' lower-tri).
__device__ __forceinline__ void mm1_32(float C[8][4], uint32_t aBase, uint32_t bBase,
                                       int lane, int row0, int col0, bool triM) {
    const uint32_t sxor = ((uint32_t)(lane & 7)) << 4;
    const uint32_t ak16 = ((lane >> 4) & 1) * 16;
    const int arowl = lane & 15;
    const int brow = ((lane >> 3) & 2) * 4 + (lane & 7);
    const uint32_t bk16 = ((lane >> 3) & 1) * 16;
    #pragma unroll
    for (int kc = 0; kc < 4; kc++) {
        uint32_t a0[4], a1[4];
        uint32_t acol = (ak16 + kc * 32) ^ sxor;
        ldsm4(aBase + (uint32_t)(row0 + arowl) * 128 + acol, a0);
        ldsm4(aBase + (uint32_t)(row0 + 16 + arowl) * 128 + acol, a1);
        #pragma unroll
        for (int g = 0; g < 2; g++) {
            int cg = col0 + g * 16;
            if (triM && kc * 16 > cg + 15) continue;   // warp-uniform skip of zero tiles
            uint32_t b[4];
            ldsm4(bBase + (uint32_t)(cg + brow) * 128 + ((bk16 + kc * 32) ^ sxor), b);
            mma_f16(C[0 + g * 2 + 0], a0, b[0], b[1]);
            mma_f16(C[0 + g * 2 + 1], a0, b[2], b[3]);
            mma_f16(C[4 + g * 2 + 0], a1, b[0], b[1]);
            mma_f16(C[4 + g * 2 + 1], a1, b[2], b[3]);
        }
    }
}

// ---------------- merged prep: x->fp16 swizzle (blocks 0-127) + per-d tiles (128-383) ----------------
__global__ void prep(const float* __restrict__ x,
                     const float* __restrict__ w_in, const float* __restrict__ b_in,
                     const float* __restrict__ A_diag, const float* __restrict__ B_in,
                     const float* __restrict__ C_out, const float* __restrict__ D_skip) {
    const int tid = threadIdx.x;
    if (blockIdx.x < 128) {
        int e = (blockIdx.x * 256 + tid) * 4;
        float4 v = *reinterpret_cast<const float4*>(x + e);
        int b = e >> 12, t = e & 4095;
        int rg = b * 64 + (t >> 6), col = t & 63;
        int boff = rg * 128 + ((col * 2) ^ ((rg & 7) << 4));
        __half2 p0 = __floats2half2_rn(v.x, v.y);
        __half2 p1 = __floats2half2_rn(v.z, v.w);
        char* p = (char*)g_x + boff;
        *(__half2*)p = p0;
        *(__half2*)(p + 4) = p1;
        return;
    }
    const int d = blockIdx.x - 128;
    const int n = tid & 63, q = tid >> 6;
    __shared__ float gmat[64][65];
    __shared__ float Kp[64][4];
    __shared__ float Ksm[64];
    __shared__ float zp[4][64];

    float a = A_diag[d * 64 + n];
    float g = B_in[d * 64 + n] * C_out[d * 64 + n];
    float a2 = a * a, a4 = a2 * a2, a8 = a4 * a4, a16 = a8 * a8;
    float a32 = a16 * a16, a48 = a32 * a16, a64v = a32 * a32;
    float s = (q == 0) ? 1.f : ((q == 1) ? a16 : ((q == 2) ? a32 : a48));

    {   // P[n][tau] = a^(63-tau); zeta partial
        float p = s, zs = 0.f;
        #pragma unroll
        for (int j = 0; j < 16; j++) {
            int e = q * 16 + j, tau = 63 - e;
            g_P[d * 4096 + swzi(n, tau)] = __float2half_rn(p);
            zs += p; p *= a;
        }
        zp[q][n] = zs;
    }
    {   // Q[i][n] = g*a^(i+1)
        float t = g * s * a;
        #pragma unroll
        for (int j = 0; j < 16; j++) {
            int i = q * 16 + j;
            g_Q[d * 4096 + swzi(i, n)] = __float2half_rn(t);
            t *= a;
        }
    }
    {   // gmat[delta][n] = g*a^delta
        float u = g * s;
        #pragma unroll
        for (int j = 0; j < 16; j++) { gmat[q * 16 + j][n] = u; u *= a; }
    }
    __syncthreads();
    if (q == 0) {
        g_zeta[d * 64 + n] = zp[0][n] + zp[1][n] + zp[2][n] + zp[3][n];
        g_aL[d * 64 + n] = a64v;
    }
    {   // K[delta] partial over n
        float ss = 0.f;
        #pragma unroll
        for (int j = 0; j < 16; j++) ss += gmat[n][q * 16 + j];
        Kp[n][q] = ss;
    }
    __syncthreads();
    if (tid < 64) Ksm[tid] = Kp[tid][0] + Kp[tid][1] + Kp[tid][2] + Kp[tid][3];
    __syncthreads();
    float w = w_in[d], bb = b_in[d], dsk = D_skip[d];
    if (tid < 64) {
        float kap = 0.f;
        for (int dd = 0; dd <= tid; dd++) kap += Ksm[dd];
        g_beta[d * 64 + tid] = bb * kap + dsk * bb;
    }
    {   // M[i][tau] = w*K[i-tau] (tau<=i), + dsk*w on diag
        int i = n;
        #pragma unroll
        for (int j = 0; j < 16; j++) {
            int tau = q * 16 + j;
            float val = (tau <= i) ? w * Ksm[i - tau] : 0.f;
            if (tau == i) val += dsk * w;
            g_M[d * 4096 + swzi(i, tau)] = __float2half_rn(val);
        }
    }
}

// ---------------- fused SSM (256 thr, 2 batches x 1 d per CTA) + tail head ----------------
__global__ __launch_bounds__(256, 3)
void ssm_mma(const float* __restrict__ w_in, const float* __restrict__ b_in,
             const float* __restrict__ W_head, const float* __restrict__ b_head,
             float* __restrict__ out) {
    extern __shared__ char smem[];
    const uint32_t sb = smem_u32(smem);
    const int tid = threadIdx.x, wid = tid >> 5, lane = tid & 31;
    const int m = blockIdx.x, d = blockIdx.y;
    const float w = w_in[d];
    const int row0 = (wid & 3) * 32;       // bc rows
    const int col0 = (wid >> 2) * 32;      // output cols (n or i)

    if (tid < 64) {
        reinterpret_cast<float*>(smem + OFF_BETA)[tid] = g_beta[d * 64 + tid];
        reinterpret_cast<float*>(smem + OFF_BZ)[tid] = b_in[d] * g_zeta[d * 64 + tid];
    }

    {   // group A: X + P (needed for MMA1)
        const char* xp = (const char*)g_x + (size_t)m * 16384;
        #pragma unroll
        for (int k = 0; k < 4; k++) {
            int i = (tid + k * 256) * 16;
            CP16(sb + OFF_X + i, xp + i);
        }
        const char* pp = (const char*)g_P + d * 8192;
        #pragma unroll
        for (int k = 0; k < 2; k++) {
            int i = (tid + k * 256) * 16;
            CP16(sb + OFF_P + i, pp + i);
        }
        CP_COMMIT();
        // group B: M + Q (needed only for MMA2)
        const char* mp = (const char*)g_M + d * 8192;
        const char* qp = (const char*)g_Q + d * 8192;
        #pragma unroll
        for (int k = 0; k < 2; k++) {
            int i = (tid + k * 256) * 16;
            CP16(sb + OFF_M + i, mp + i);
            CP16(sb + OFF_Q + i, qp + i);
        }
        CP_COMMIT();
    }
    CP_WAIT(1);        // X+P landed; M+Q may still be in flight
    __syncthreads();

    // MMA1: F = X . P^T
    float C1[8][4];
    #pragma unroll
    for (int i = 0; i < 8; i++)
        #pragma unroll
        for (int k = 0; k < 4; k++) C1[i][k] = 0.f;
    mm1_32(C1, sb + OFF_X, sb + OFF_P, lane, row0, col0, false);

    {   // store f = w*F + bz[n] as fp16 into SF (swizzled 128B pitch)
        const float* bz = reinterpret_cast<const float*>(smem + OFF_BZ);
        int rl4 = lane >> 2, cb = (lane & 3) * 2;
        #pragma unroll
        for (int mt = 0; mt < 2; mt++)
            #pragma unroll
            for (int g = 0; g < 2; g++)
                #pragma unroll
                for (int h = 0; h < 2; h++) {
                    int idx = mt * 4 + g * 2 + h;
                    int colb = col0 + g * 16 + h * 8 + cb;
                    float2 bz2 = *reinterpret_cast<const float2*>(bz + colb);
                    int r0 = row0 + mt * 16 + rl4;
                    *reinterpret_cast<__half2*>(smem + OFF_SF + r0 * 128 +
                            ((colb * 2) ^ ((r0 & 7) << 4))) =
                        __floats2half2_rn(fmaf(w, C1[idx][0], bz2.x), fmaf(w, C1[idx][1], bz2.y));
                    int r1 = r0 + 8;
                    *reinterpret_cast<__half2*>(smem + OFF_SF + r1 * 128 +
                            ((colb * 2) ^ ((r1 & 7) << 4))) =
                        __floats2half2_rn(fmaf(w, C1[idx][2], bz2.x), fmaf(w, C1[idx][3], bz2.y));
                }
    }
    __syncthreads();

    // scan (tid<128): segmented, pipelined; read f, overwrite with seed
    if (tid < 128) {
        int bl = tid >> 6, n = tid & 63;
        float aLv = g_aL[d * 64 + n];
        float r = 0.f;
        const uint32_t colx = (uint32_t)(n * 2);
        #pragma unroll
        for (int seg = 0; seg < 4; seg++) {
            float fv[16];
            #pragma unroll
            for (int j = 0; j < 16; j++) {
                int c = seg * 16 + j;
                fv[j] = __half2float(*reinterpret_cast<const __half*>(
                    smem + OFF_SF + (bl * 64 + c) * 128 + (colx ^ ((c & 7) << 4))));
            }
            #pragma unroll
            for (int j = 0; j < 16; j++) {
                int c = seg * 16 + j;
                *reinterpret_cast<__half*>(
                    smem + OFF_SF + (bl * 64 + c) * 128 + (colx ^ ((c & 7) << 4))) =
                    __float2half_rn(r);
                r = fmaf(aLv, r, fv[j]);
            }
        }
    }
    CP_WAIT(0);        // M + Q landed (long since, usually)
    __syncthreads();

    // MMA2: y = X.M'^T (lower-tri skip) + S.Q^T ; epilogue gelu+pool
    float C2[8][4];
    #pragma unroll
    for (int i = 0; i < 8; i++)
        #pragma unroll
        for (int k = 0; k < 4; k++) C2[i][k] = 0.f;
    mm1_32(C2, sb + OFF_X, sb + OFF_M, lane, row0, col0, true);
    mm1_32(C2, sb + OFF_SF, sb + OFF_Q, lane, row0, col0, false);

    {
        const float* beta = reinterpret_cast<const float*>(smem + OFF_BETA);
        int cb = (lane & 3) * 2;
        float ps = 0.f, pm = -3.402823466e38f;
        #pragma unroll
        for (int mt = 0; mt < 2; mt++)
            #pragma unroll
            for (int g = 0; g < 2; g++)
                #pragma unroll
                for (int h = 0; h < 2; h++) {
                    int idx = mt * 4 + g * 2 + h;
                    float2 b2 = *reinterpret_cast<const float2*>(
                        beta + col0 + g * 16 + h * 8 + cb);
                    #pragma unroll
                    for (int k = 0; k < 4; k++) {
                        float ypre = C2[idx][k] + ((k & 1) ? b2.y : b2.x);
                        float inner = 0.7978845608028654f * ypre * fmaf(0.044715f, ypre * ypre, 1.0f);
                        float th; asm("tanh.approx.f32 %0, %1;" : "=f"(th) : "f"(inner));
                        float hh = 0.5f * ypre * (1.0f + th);
                        ps += hh;
                        pm = fmaxf(pm, hh);
                    }
                }
        #pragma unroll
        for (int o = 16; o > 0; o >>= 1) {
            ps += __shfl_xor_sync(0xffffffffu, ps, o);
            pm = fmaxf(pm, __shfl_xor_sync(0xffffffffu, pm, o));
        }
        float* wp = reinterpret_cast<float*>(smem + OFF_WP);
        if (lane == 0) { wp[wid * 2] = ps; wp[wid * 2 + 1] = pm; }
    }
    __syncthreads();
    if (tid < 2) {
        // batch0: warps 0,1,4,5 (row0<64) ; batch1: warps 2,3,6,7
        const float* wp = reinterpret_cast<const float*>(smem + OFF_WP);
        int w0 = tid * 2;
        float s = wp[(w0 + 0) * 2] + wp[(w0 + 1) * 2] + wp[(w0 + 4) * 2] + wp[(w0 + 5) * 2];
        float mx = fmaxf(fmaxf(wp[(w0 + 0) * 2 + 1], wp[(w0 + 1) * 2 + 1]),
                         fmaxf(wp[(w0 + 4) * 2 + 1], wp[(w0 + 5) * 2 + 1]));
        int b = m * 2 + tid;
        g_pool[(b * DM + d) * 2] = s;
        g_pool[(b * DM + d) * 2 + 1] = mx;
    }

    // ---- last-CTA head ----
    __shared__ unsigned int s_last;
    __threadfence();
    __syncthreads();
    if (tid == 0) {
        unsigned int v = atomicAdd(&g_ctr, 1u);
        s_last = (v == TOTAL_CTAS - 1) ? 1u : 0u;
    }
    __syncthreads();
    if (s_last) {
        __threadfence();   // acquire all pool writes
        #pragma unroll
        for (int bb = 0; bb < 4; bb++) {
            int b = wid * 4 + bb;
            float acc[NCLS];
            #pragma unroll
            for (int k = 0; k < NCLS; k++) acc[k] = 0.f;
            #pragma unroll
            for (int j = 0; j < 16; j++) {
                int dd = lane + j * 32;          // 0..511
                float v;
                if (dd < DM) v = g_pool[(b * DM + dd) * 2] * (1.0f / (float)T_TOTAL);
                else         v = g_pool[(b * DM + (dd - DM)) * 2 + 1];
                #pragma unroll
                for (int k = 0; k < NCLS; k++)
                    acc[k] = fmaf(v, W_head[dd * NCLS + k], acc[k]);
            }
            #pragma unroll
            for (int k = 0; k < NCLS; k++) {
                float v = acc[k];
                #pragma unroll
                for (int o = 16; o > 0; o >>= 1) v += __shfl_xor_sync(0xffffffffu, v, o);
                if (lane == 0) out[b * NCLS + k] = v + b_head[k];
            }
        }
        __syncthreads();
        if (tid == 0) g_ctr = 0;   // reset for next graph replay
    }
}

extern "C" void kernel_launch(void* const* d_in, const int* in_sizes, int n_in,
                              void* d_out, int out_size) {
    const float* x      = (const float*)d_in[0];
    const float* w_in   = (const float*)d_in[1];
    const float* b_in   = (const float*)d_in[2];
    const float* A_diag = (const float*)d_in[3];
    const float* B_in   = (const float*)d_in[4];
    const float* C_out  = (const float*)d_in[5];
    const float* D_skip = (const float*)d_in[6];
    const float* W_head = (const float*)d_in[7];
    const float* b_head = (const float*)d_in[8];
    float* out = (float*)d_out;

    cudaFuncSetAttribute(ssm_mma, cudaFuncAttributeMaxDynamicSharedMemorySize, SMEM_BYTES);
    prep<<<384, 256>>>(x, w_in, b_in, A_diag, B_in, C_out, D_skip);
    ssm_mma<<<dim3(MT, DM), 256, SMEM_BYTES>>>(w_in, b_in, W_head, b_head, out);
}

// round 13
// speedup vs baseline: 1.7222x; 1.3082x over previous
#include <cuda_runtime.h>
#include <cuda_fp16.h>
#include <cstdint>

#define BATCH 32
#define T_TOTAL 4096
#define DM 256
#define SN 64
#define NCLS 5
#define L 64
#define MT 16                  /* 128-row tiles: 2 batches per CTA */
#define TOTAL_CTAS (MT * DM)   /* 4096 */

// ---- gmem precomputed operands (pre-swizzled fp16) ----
__device__ __half g_x[BATCH * T_TOTAL];
__device__ __half g_P[DM * 4096];
__device__ __half g_M[DM * 4096];
__device__ __half g_Q[DM * 4096];
__device__ float g_beta[DM * L], g_zeta[DM * SN], g_aL[DM * SN];
__device__ float g_pool[BATCH * DM * 2];
__device__ unsigned int g_ctr = 0;

// ---- smem layout (bytes) for ssm_mma ----
#define OFF_BETA 0                 /* 64 f32 */
#define OFF_WP   256               /* 16 f32 */
#define OFF_BZ   320               /* 64 f32: b*zeta[n] */
#define OFF_X    640               /* 128 x 128B fp16 */
#define OFF_SF   17024             /* f (MMA1 out) then seeds: 128 x 128B */
#define OFF_P    33408             /* 64 x 128B */
#define OFF_M    41600             /* 64 x 128B */
#define OFF_Q    49792             /* 64 x 128B */
#define SMEM_BYTES 57984

__device__ __forceinline__ uint32_t smem_u32(const void* p) {
    uint32_t a;
    asm("{ .reg .u64 t; cvta.to.shared.u64 t, %1; cvt.u32.u64 %0, t; }" : "=r"(a) : "l"(p));
    return a;
}
#define CP16(dst, src) asm volatile("cp.async.cg.shared.global [%0], [%1], 16;" :: "r"(dst), "l"(src))
#define CP_COMMIT()    asm volatile("cp.async.commit_group;" ::: "memory")
#define CP_WAIT(n)     asm volatile("cp.async.wait_group %0;" :: "n"(n) : "memory")

__device__ __forceinline__ void ldsm4(uint32_t addr, uint32_t r[4]) {
    asm volatile("ldmatrix.sync.aligned.m8n8.x4.shared.b16 {%0,%1,%2,%3}, [%4];"
                 : "=r"(r[0]), "=r"(r[1]), "=r"(r[2]), "=r"(r[3]) : "r"(addr));
}
__device__ __forceinline__ void mma_f16(float c[4], const uint32_t a[4], uint32_t b0, uint32_t b1) {
    asm volatile("mma.sync.aligned.m16n8k16.row.col.f32.f16.f16.f32 "
                 "{%0,%1,%2,%3}, {%4,%5,%6,%7}, {%8,%9}, {%0,%1,%2,%3};"
                 : "+f"(c[0]), "+f"(c[1]), "+f"(c[2]), "+f"(c[3])
                 : "r"(a[0]), "r"(a[1]), "r"(a[2]), "r"(a[3]), "r"(b0), "r"(b1));
}
// swizzled elem index within a 128B-row fp16 tile
__device__ __forceinline__ int swzi(int row, int col) {
    return ((row * 128 + col * 2) ^ ((row & 7) << 4)) >> 1;
}

// 32x32 warp-tile fp16 matmul-accumulate over K=64:
// C covers rows [row0,row0+32) x cols [col0,col0+32). triM: skip tiles with tau>i (M' lower-tri).
__device__ __forceinline__ void mm1_32(float C[8][4], uint32_t aBase, uint32_t bBase,
                                       int lane, int row0, int col0, bool triM) {
    const uint32_t sxor = ((uint32_t)(lane & 7)) << 4;
    const uint32_t ak16 = ((lane >> 4) & 1) * 16;
    const int arowl = lane & 15;
    const int brow = ((lane >> 3) & 2) * 4 + (lane & 7);
    const uint32_t bk16 = ((lane >> 3) & 1) * 16;
    #pragma unroll
    for (int kc = 0; kc < 4; kc++) {
        uint32_t a0[4], a1[4];
        uint32_t acol = (ak16 + kc * 32) ^ sxor;
        ldsm4(aBase + (uint32_t)(row0 + arowl) * 128 + acol, a0);
        ldsm4(aBase + (uint32_t)(row0 + 16 + arowl) * 128 + acol, a1);
        #pragma unroll
        for (int g = 0; g < 2; g++) {
            int cg = col0 + g * 16;
            if (triM && kc * 16 > cg + 15) continue;   // warp-uniform skip of zero tiles
            uint32_t b[4];
            ldsm4(bBase + (uint32_t)(cg + brow) * 128 + ((bk16 + kc * 32) ^ sxor), b);
            mma_f16(C[0 + g * 2 + 0], a0, b[0], b[1]);
            mma_f16(C[0 + g * 2 + 1], a0, b[2], b[3]);
            mma_f16(C[4 + g * 2 + 0], a1, b[0], b[1]);
            mma_f16(C[4 + g * 2 + 1], a1, b[2], b[3]);
        }
    }
}

// ---------------- merged prep: x->fp16 swizzle (blocks 0-127) + per-d tiles (128-383) ----------------
// d-part: identical arithmetic to R12, but P/Q/M staged in smem and written out coalesced.
__global__ void prep(const float* __restrict__ x,
                     const float* __restrict__ w_in, const float* __restrict__ b_in,
                     const float* __restrict__ A_diag, const float* __restrict__ B_in,
                     const float* __restrict__ C_out, const float* __restrict__ D_skip) {
    const int tid = threadIdx.x;
    if (blockIdx.x < 128) {
        int e = (blockIdx.x * 256 + tid) * 4;
        float4 v = *reinterpret_cast<const float4*>(x + e);
        int b = e >> 12, t = e & 4095;
        int rg = b * 64 + (t >> 6), col = t & 63;
        int boff = rg * 128 + ((col * 2) ^ ((rg & 7) << 4));
        __half2 p0 = __floats2half2_rn(v.x, v.y);
        __half2 p1 = __floats2half2_rn(v.z, v.w);
        char* p = (char*)g_x + boff;
        *(__half2*)p = p0;
        *(__half2*)(p + 4) = p1;
        return;
    }
    const int d = blockIdx.x - 128;
    const int n = tid & 63, q = tid >> 6;
    __shared__ float gmat[64][65];
    __shared__ float Kp[64][4];
    __shared__ float Ksm[64];
    __shared__ float zp[4][64];
    __shared__ __half sP[4096];     // staging buffers: swizzled tiles
    __shared__ __half sQ[4096];

    float a = A_diag[d * 64 + n];
    float g = B_in[d * 64 + n] * C_out[d * 64 + n];
    float a2 = a * a, a4 = a2 * a2, a8 = a4 * a4, a16 = a8 * a8;
    float a32 = a16 * a16, a48 = a32 * a16, a64v = a32 * a32;
    float s = (q == 0) ? 1.f : ((q == 1) ? a16 : ((q == 2) ? a32 : a48));

    {   // P[n][tau] = a^(63-tau); zeta partial
        float p = s, zs = 0.f;
        #pragma unroll
        for (int j = 0; j < 16; j++) {
            int e = q * 16 + j, tau = 63 - e;
            sP[swzi(n, tau)] = __float2half_rn(p);
            zs += p; p *= a;
        }
        zp[q][n] = zs;
    }
    {   // Q[i][n] = g*a^(i+1)
        float t = g * s * a;
        #pragma unroll
        for (int j = 0; j < 16; j++) {
            int i = q * 16 + j;
            sQ[swzi(i, n)] = __float2half_rn(t);
            t *= a;
        }
    }
    {   // gmat[delta][n] = g*a^delta
        float u = g * s;
        #pragma unroll
        for (int j = 0; j < 16; j++) { gmat[q * 16 + j][n] = u; u *= a; }
    }
    __syncthreads();
    // coalesced copy-out of P and Q (int4 = 8 halves, sequential)
    {
        const int4* srcP = reinterpret_cast<const int4*>(sP);
        const int4* srcQ = reinterpret_cast<const int4*>(sQ);
        int4* dstP = reinterpret_cast<int4*>(g_P + d * 4096);
        int4* dstQ = reinterpret_cast<int4*>(g_Q + d * 4096);
        #pragma unroll
        for (int k = 0; k < 2; k++) {
            dstP[tid + k * 256] = srcP[tid + k * 256];
            dstQ[tid + k * 256] = srcQ[tid + k * 256];
        }
    }
    if (q == 0) {
        g_zeta[d * 64 + n] = zp[0][n] + zp[1][n] + zp[2][n] + zp[3][n];
        g_aL[d * 64 + n] = a64v;
    }
    {   // K[delta] partial over n
        float ss = 0.f;
        #pragma unroll
        for (int j = 0; j < 16; j++) ss += gmat[n][q * 16 + j];
        Kp[n][q] = ss;
    }
    __syncthreads();
    if (tid < 64) Ksm[tid] = Kp[tid][0] + Kp[tid][1] + Kp[tid][2] + Kp[tid][3];
    __syncthreads();
    float w = w_in[d], bb = b_in[d], dsk = D_skip[d];
    if (tid < 64) {
        float kap = 0.f;
        for (int dd = 0; dd <= tid; dd++) kap += Ksm[dd];
        g_beta[d * 64 + tid] = bb * kap + dsk * bb;
    }
    {   // M[i][tau] = w*K[i-tau] (tau<=i), + dsk*w on diag  -> stage into sP (dead)
        int i = n;
        #pragma unroll
        for (int j = 0; j < 16; j++) {
            int tau = q * 16 + j;
            float val = (tau <= i) ? w * Ksm[i - tau] : 0.f;
            if (tau == i) val += dsk * w;
            sP[swzi(i, tau)] = __float2half_rn(val);
        }
    }
    __syncthreads();
    {   // coalesced copy-out of M
        const int4* srcM = reinterpret_cast<const int4*>(sP);
        int4* dstM = reinterpret_cast<int4*>(g_M + d * 4096);
        #pragma unroll
        for (int k = 0; k < 2; k++)
            dstM[tid + k * 256] = srcM[tid + k * 256];
    }
}

// ---------------- fused SSM (256 thr, 2 batches x 1 d per CTA) + tail head ----------------
__global__ __launch_bounds__(256, 3)
void ssm_mma(const float* __restrict__ w_in, const float* __restrict__ b_in,
             const float* __restrict__ W_head, const float* __restrict__ b_head,
             float* __restrict__ out) {
    extern __shared__ char smem[];
    const uint32_t sb = smem_u32(smem);
    const int tid = threadIdx.x, wid = tid >> 5, lane = tid & 31;
    const int m = blockIdx.x, d = blockIdx.y;
    const float w = w_in[d];
    const int row0 = (wid & 3) * 32;       // bc rows
    const int col0 = (wid >> 2) * 32;      // output cols (n or i)

    if (tid < 64) {
        reinterpret_cast<float*>(smem + OFF_BETA)[tid] = g_beta[d * 64 + tid];
        reinterpret_cast<float*>(smem + OFF_BZ)[tid] = b_in[d] * g_zeta[d * 64 + tid];
    }

    {   // group A: X + P (needed for MMA1)
        const char* xp = (const char*)g_x + (size_t)m * 16384;
        #pragma unroll
        for (int k = 0; k < 4; k++) {
            int i = (tid + k * 256) * 16;
            CP16(sb + OFF_X + i, xp + i);
        }
        const char* pp = (const char*)g_P + d * 8192;
        #pragma unroll
        for (int k = 0; k < 2; k++) {
            int i = (tid + k * 256) * 16;
            CP16(sb + OFF_P + i, pp + i);
        }
        CP_COMMIT();
        // group B: M + Q (needed only for MMA2)
        const char* mp = (const char*)g_M + d * 8192;
        const char* qp = (const char*)g_Q + d * 8192;
        #pragma unroll
        for (int k = 0; k < 2; k++) {
            int i = (tid + k * 256) * 16;
            CP16(sb + OFF_M + i, mp + i);
            CP16(sb + OFF_Q + i, qp + i);
        }
        CP_COMMIT();
    }
    CP_WAIT(1);        // X+P landed; M+Q may still be in flight
    __syncthreads();

    // MMA1: F = X . P^T
    float C1[8][4];
    #pragma unroll
    for (int i = 0; i < 8; i++)
        #pragma unroll
        for (int k = 0; k < 4; k++) C1[i][k] = 0.f;
    mm1_32(C1, sb + OFF_X, sb + OFF_P, lane, row0, col0, false);

    {   // store f = w*F + bz[n] as fp16 into SF (swizzled 128B pitch)
        const float* bz = reinterpret_cast<const float*>(smem + OFF_BZ);
        int rl4 = lane >> 2, cb = (lane & 3) * 2;
        #pragma unroll
        for (int mt = 0; mt < 2; mt++)
            #pragma unroll
            for (int g = 0; g < 2; g++)
                #pragma unroll
                for (int h = 0; h < 2; h++) {
                    int idx = mt * 4 + g * 2 + h;
                    int colb = col0 + g * 16 + h * 8 + cb;
                    float2 bz2 = *reinterpret_cast<const float2*>(bz + colb);
                    int r0 = row0 + mt * 16 + rl4;
                    *reinterpret_cast<__half2*>(smem + OFF_SF + r0 * 128 +
                            ((colb * 2) ^ ((r0 & 7) << 4))) =
                        __floats2half2_rn(fmaf(w, C1[idx][0], bz2.x), fmaf(w, C1[idx][1], bz2.y));
                    int r1 = r0 + 8;
                    *reinterpret_cast<__half2*>(smem + OFF_SF + r1 * 128 +
                            ((colb * 2) ^ ((r1 & 7) << 4))) =
                        __floats2half2_rn(fmaf(w, C1[idx][2], bz2.x), fmaf(w, C1[idx][3], bz2.y));
                }
    }
    __syncthreads();

    // scan (tid<128): segmented, pipelined; read f, overwrite with seed
    if (tid < 128) {
        int bl = tid >> 6, n = tid & 63;
        float aLv = g_aL[d * 64 + n];
        float r = 0.f;
        const uint32_t colx = (uint32_t)(n * 2);
        #pragma unroll
        for (int seg = 0; seg < 4; seg++) {
            float fv[16];
            #pragma unroll
            for (int j = 0; j < 16; j++) {
                int c = seg * 16 + j;
                fv[j] = __half2float(*reinterpret_cast<const __half*>(
                    smem + OFF_SF + (bl * 64 + c) * 128 + (colx ^ ((c & 7) << 4))));
            }
            #pragma unroll
            for (int j = 0; j < 16; j++) {
                int c = seg * 16 + j;
                *reinterpret_cast<__half*>(
                    smem + OFF_SF + (bl * 64 + c) * 128 + (colx ^ ((c & 7) << 4))) =
                    __float2half_rn(r);
                r = fmaf(aLv, r, fv[j]);
            }
        }
    }
    CP_WAIT(0);        // M + Q landed (long since, usually)
    __syncthreads();

    // MMA2: y = X.M'^T (lower-tri skip) + S.Q^T ; epilogue gelu+pool
    float C2[8][4];
    #pragma unroll
    for (int i = 0; i < 8; i++)
        #pragma unroll
        for (int k = 0; k < 4; k++) C2[i][k] = 0.f;
    mm1_32(C2, sb + OFF_X, sb + OFF_M, lane, row0, col0, true);
    mm1_32(C2, sb + OFF_SF, sb + OFF_Q, lane, row0, col0, false);

    {
        const float* beta = reinterpret_cast<const float*>(smem + OFF_BETA);
        int cb = (lane & 3) * 2;
        float ps = 0.f, pm = -3.402823466e38f;
        #pragma unroll
        for (int mt = 0; mt < 2; mt++)
            #pragma unroll
            for (int g = 0; g < 2; g++)
                #pragma unroll
                for (int h = 0; h < 2; h++) {
                    int idx = mt * 4 + g * 2 + h;
                    float2 b2 = *reinterpret_cast<const float2*>(
                        beta + col0 + g * 16 + h * 8 + cb);
                    #pragma unroll
                    for (int k = 0; k < 4; k++) {
                        float ypre = C2[idx][k] + ((k & 1) ? b2.y : b2.x);
                        float inner = 0.7978845608028654f * ypre * fmaf(0.044715f, ypre * ypre, 1.0f);
                        float th; asm("tanh.approx.f32 %0, %1;" : "=f"(th) : "f"(inner));
                        float hh = 0.5f * ypre * (1.0f + th);
                        ps += hh;
                        pm = fmaxf(pm, hh);
                    }
                }
        #pragma unroll
        for (int o = 16; o > 0; o >>= 1) {
            ps += __shfl_xor_sync(0xffffffffu, ps, o);
            pm = fmaxf(pm, __shfl_xor_sync(0xffffffffu, pm, o));
        }
        float* wp = reinterpret_cast<float*>(smem + OFF_WP);
        if (lane == 0) { wp[wid * 2] = ps; wp[wid * 2 + 1] = pm; }
    }
    __syncthreads();
    if (tid < 2) {
        // batch0: warps 0,1,4,5 (row0<64) ; batch1: warps 2,3,6,7
        const float* wp = reinterpret_cast<const float*>(smem + OFF_WP);
        int w0 = tid * 2;
        float s = wp[(w0 + 0) * 2] + wp[(w0 + 1) * 2] + wp[(w0 + 4) * 2] + wp[(w0 + 5) * 2];
        float mx = fmaxf(fmaxf(wp[(w0 + 0) * 2 + 1], wp[(w0 + 1) * 2 + 1]),
                         fmaxf(wp[(w0 + 4) * 2 + 1], wp[(w0 + 5) * 2 + 1]));
        int b = m * 2 + tid;
        g_pool[(b * DM + d) * 2] = s;
        g_pool[(b * DM + d) * 2 + 1] = mx;
    }

    // ---- last-CTA head ----
    __shared__ unsigned int s_last;
    __threadfence();
    __syncthreads();
    if (tid == 0) {
        unsigned int v = atomicAdd(&g_ctr, 1u);
        s_last = (v == TOTAL_CTAS - 1) ? 1u : 0u;
    }
    __syncthreads();
    if (s_last) {
        __threadfence();   // acquire all pool writes
        #pragma unroll
        for (int bb = 0; bb < 4; bb++) {
            int b = wid * 4 + bb;
            float acc[NCLS];
            #pragma unroll
            for (int k = 0; k < NCLS; k++) acc[k] = 0.f;
            #pragma unroll
            for (int j = 0; j < 16; j++) {
                int dd = lane + j * 32;          // 0..511
                float v;
                if (dd < DM) v = g_pool[(b * DM + dd) * 2] * (1.0f / (float)T_TOTAL);
                else         v = g_pool[(b * DM + (dd - DM)) * 2 + 1];
                #pragma unroll
                for (int k = 0; k < NCLS; k++)
                    acc[k] = fmaf(v, W_head[dd * NCLS + k], acc[k]);
            }
            #pragma unroll
            for (int k = 0; k < NCLS; k++) {
                float v = acc[k];
                #pragma unroll
                for (int o = 16; o > 0; o >>= 1) v += __shfl_xor_sync(0xffffffffu, v, o);
                if (lane == 0) out[b * NCLS + k] = v + b_head[k];
            }
        }
        __syncthreads();
        if (tid == 0) g_ctr = 0;   // reset for next graph replay
    }
}

extern "C" void kernel_launch(void* const* d_in, const int* in_sizes, int n_in,
                              void* d_out, int out_size) {
    const float* x      = (const float*)d_in[0];
    const float* w_in   = (const float*)d_in[1];
    const float* b_in   = (const float*)d_in[2];
    const float* A_diag = (const float*)d_in[3];
    const float* B_in   = (const float*)d_in[4];
    const float* C_out  = (const float*)d_in[5];
    const float* D_skip = (const float*)d_in[6];
    const float* W_head = (const float*)d_in[7];
    const float* b_head = (const float*)d_in[8];
    float* out = (float*)d_out;

    cudaFuncSetAttribute(ssm_mma, cudaFuncAttributeMaxDynamicSharedMemorySize, SMEM_BYTES);
    prep<<<384, 256>>>(x, w_in, b_in, A_diag, B_in, C_out, D_skip);
    ssm_mma<<<dim3(MT, DM), 256, SMEM_BYTES>>>(w_in, b_in, W_head, b_head, out);
}

// round 16
// speedup vs baseline: 1.7581x; 1.0208x over previous
#include <cuda_runtime.h>
#include <cuda_fp16.h>
#include <cstdint>

#define BATCH 32
#define T_TOTAL 4096
#define DM 256
#define SN 64
#define NCLS 5
#define L 64
#define MT 16                  /* 128-row tiles: 2 batches per CTA */
#define TOTAL_CTAS (MT * (DM / 2))   /* 2048: each CTA does d0, d0+1 */

// ---- gmem precomputed operands (pre-swizzled fp16) ----
__device__ __half g_x[BATCH * T_TOTAL];
__device__ __half g_P[DM * 4096];
__device__ __half g_M[DM * 4096];
__device__ __half g_Q[DM * 4096];
__device__ float g_beta[DM * L], g_zeta[DM * SN], g_aL[DM * SN];
__device__ float g_pool[BATCH * DM * 2];
__device__ unsigned int g_ctr = 0;

// ---- smem layout (bytes) for ssm_mma ----
#define OFF_BETA 0                 /* 2 x 64 f32 (per half) */
#define OFF_WP   512               /* 16 f32 */
#define OFF_BZ   576               /* 2 x 64 f32 (per half) */
#define OFF_X    1152              /* 128 x 128B fp16 (128B-aligned) */
#define OFF_SF   17536             /* f (MMA1 out) then seeds: 128 x 128B */
#define OFF_P    33920             /* 64 x 128B */
#define OFF_M    42112             /* 64 x 128B */
#define OFF_Q    50304             /* 64 x 128B */
#define SMEM_BYTES 58496

__device__ __forceinline__ uint32_t smem_u32(const void* p) {
    uint32_t a;
    asm("{ .reg .u64 t; cvta.to.shared.u64 t, %1; cvt.u32.u64 %0, t; }" : "=r"(a) : "l"(p));
    return a;
}
#define CP16(dst, src) asm volatile("cp.async.cg.shared.global [%0], [%1], 16;" :: "r"(dst), "l"(src))
#define CP_COMMIT()    asm volatile("cp.async.commit_group;" ::: "memory")
#define CP_WAIT(n)     asm volatile("cp.async.wait_group %0;" :: "n"(n) : "memory")

__device__ __forceinline__ void ldsm4(uint32_t addr, uint32_t r[4]) {
    asm volatile("ldmatrix.sync.aligned.m8n8.x4.shared.b16 {%0,%1,%2,%3}, [%4];"
                 : "=r"(r[0]), "=r"(r[1]), "=r"(r[2]), "=r"(r[3]) : "r"(addr));
}
__device__ __forceinline__ void mma_f16(float c[4], const uint32_t a[4], uint32_t b0, uint32_t b1) {
    asm volatile("mma.sync.aligned.m16n8k16.row.col.f32.f16.f16.f32 "
                 "{%0,%1,%2,%3}, {%4,%5,%6,%7}, {%8,%9}, {%0,%1,%2,%3};"
                 : "+f"(c[0]), "+f"(c[1]), "+f"(c[2]), "+f"(c[3])
                 : "r"(a[0]), "r"(a[1]), "r"(a[2]), "r"(a[3]), "r"(b0), "r"(b1));
}
// swizzled elem index within a 128B-row fp16 tile
__device__ __forceinline__ int swzi(int row, int col) {
    return ((row * 128 + col * 2) ^ ((row & 7) << 4)) >> 1;
}

// 32x32 warp-tile fp16 matmul-accumulate over K=64:
// C covers rows [row0,row0+32) x cols [col0,col0+32). triM: skip tiles with tau>i (M' lower-tri).
__device__ __forceinline__ void mm1_32(float C[8][4], uint32_t aBase, uint32_t bBase,
                                       int lane, int row0, int col0, bool triM) {
    const uint32_t sxor = ((uint32_t)(lane & 7)) << 4;
    const uint32_t ak16 = ((lane >> 4) & 1) * 16;
    const int arowl = lane & 15;
    const int brow = ((lane >> 3) & 2) * 4 + (lane & 7);
    const uint32_t bk16 = ((lane >> 3) & 1) * 16;
    #pragma unroll
    for (int kc = 0; kc < 4; kc++) {
        uint32_t a0[4], a1[4];
        uint32_t acol = (ak16 + kc * 32) ^ sxor;
        ldsm4(aBase + (uint32_t)(row0 + arowl) * 128 + acol, a0);
        ldsm4(aBase + (uint32_t)(row0 + 16 + arowl) * 128 + acol, a1);
        #pragma unroll
        for (int g = 0; g < 2; g++) {
            int cg = col0 + g * 16;
            if (triM && kc * 16 > cg + 15) continue;   // warp-uniform skip of zero tiles
            uint32_t b[4];
            ldsm4(bBase + (uint32_t)(cg + brow) * 128 + ((bk16 + kc * 32) ^ sxor), b);
            mma_f16(C[0 + g * 2 + 0], a0, b[0], b[1]);
            mma_f16(C[0 + g * 2 + 1], a0, b[2], b[3]);
            mma_f16(C[4 + g * 2 + 0], a1, b[0], b[1]);
            mma_f16(C[4 + g * 2 + 1], a1, b[2], b[3]);
        }
    }
}

// ---------------- merged prep: x->fp16 swizzle (blocks 0-127) + per-d tiles (128-383) ----------------
__global__ void prep(const float* __restrict__ x,
                     const float* __restrict__ w_in, const float* __restrict__ b_in,
                     const float* __restrict__ A_diag, const float* __restrict__ B_in,
                     const float* __restrict__ C_out, const float* __restrict__ D_skip) {
    const int tid = threadIdx.x;
    if (blockIdx.x < 128) {
        int e = (blockIdx.x * 256 + tid) * 4;
        float4 v = *reinterpret_cast<const float4*>(x + e);
        int b = e >> 12, t = e & 4095;
        int rg = b * 64 + (t >> 6), col = t & 63;
        int boff = rg * 128 + ((col * 2) ^ ((rg & 7) << 4));
        __half2 p0 = __floats2half2_rn(v.x, v.y);
        __half2 p1 = __floats2half2_rn(v.z, v.w);
        char* p = (char*)g_x + boff;
        *(__half2*)p = p0;
        *(__half2*)(p + 4) = p1;
        return;
    }
    const int d = blockIdx.x - 128;
    const int n = tid & 63, q = tid >> 6;
    __shared__ float gmat[64][65];
    __shared__ float Kp[64][4];
    __shared__ float Ksm[64];
    __shared__ float zp[4][64];
    __shared__ __half sP[4096];     // staging buffers: swizzled tiles
    __shared__ __half sQ[4096];

    float a = A_diag[d * 64 + n];
    float g = B_in[d * 64 + n] * C_out[d * 64 + n];
    float a2 = a * a, a4 = a2 * a2, a8 = a4 * a4, a16 = a8 * a8;
    float a32 = a16 * a16, a48 = a32 * a16, a64v = a32 * a32;
    float s = (q == 0) ? 1.f : ((q == 1) ? a16 : ((q == 2) ? a32 : a48));

    {   // P[n][tau] = a^(63-tau); zeta partial
        float p = s, zs = 0.f;
        #pragma unroll
        for (int j = 0; j < 16; j++) {
            int e = q * 16 + j, tau = 63 - e;
            sP[swzi(n, tau)] = __float2half_rn(p);
            zs += p; p *= a;
        }
        zp[q][n] = zs;
    }
    {   // Q[i][n] = g*a^(i+1)
        float t = g * s * a;
        #pragma unroll
        for (int j = 0; j < 16; j++) {
            int i = q * 16 + j;
            sQ[swzi(i, n)] = __float2half_rn(t);
            t *= a;
        }
    }
    {   // gmat[delta][n] = g*a^delta
        float u = g * s;
        #pragma unroll
        for (int j = 0; j < 16; j++) { gmat[q * 16 + j][n] = u; u *= a; }
    }
    __syncthreads();
    {   // coalesced copy-out of P and Q
        const int4* srcP = reinterpret_cast<const int4*>(sP);
        const int4* srcQ = reinterpret_cast<const int4*>(sQ);
        int4* dstP = reinterpret_cast<int4*>(g_P + d * 4096);
        int4* dstQ = reinterpret_cast<int4*>(g_Q + d * 4096);
        #pragma unroll
        for (int k = 0; k < 2; k++) {
            dstP[tid + k * 256] = srcP[tid + k * 256];
            dstQ[tid + k * 256] = srcQ[tid + k * 256];
        }
    }
    if (q == 0) {
        g_zeta[d * 64 + n] = zp[0][n] + zp[1][n] + zp[2][n] + zp[3][n];
        g_aL[d * 64 + n] = a64v;
    }
    {   // K[delta] partial over n
        float ss = 0.f;
        #pragma unroll
        for (int j = 0; j < 16; j++) ss += gmat[n][q * 16 + j];
        Kp[n][q] = ss;
    }
    __syncthreads();
    if (tid < 64) Ksm[tid] = Kp[tid][0] + Kp[tid][1] + Kp[tid][2] + Kp[tid][3];
    __syncthreads();
    float w = w_in[d], bb = b_in[d], dsk = D_skip[d];
    if (tid < 64) {
        float kap = 0.f;
        for (int dd = 0; dd <= tid; dd++) kap += Ksm[dd];
        g_beta[d * 64 + tid] = bb * kap + dsk * bb;
    }
    {   // M[i][tau] = w*K[i-tau] (tau<=i), + dsk*w on diag  -> stage into sP (dead)
        int i = n;
        #pragma unroll
        for (int j = 0; j < 16; j++) {
            int tau = q * 16 + j;
            float val = (tau <= i) ? w * Ksm[i - tau] : 0.f;
            if (tau == i) val += dsk * w;
            sP[swzi(i, tau)] = __float2half_rn(val);
        }
    }
    __syncthreads();
    {   // coalesced copy-out of M
        const int4* srcM = reinterpret_cast<const int4*>(sP);
        int4* dstM = reinterpret_cast<int4*>(g_M + d * 4096);
        #pragma unroll
        for (int k = 0; k < 2; k++)
            dstM[tid + k * 256] = srcM[tid + k * 256];
    }
}

// ---------------- per-half building blocks for ssm_mma ----------------
__device__ __forceinline__ void half_mma1_fstore(char* smem, uint32_t sb, int lane, int wid,
                                                 int row0, int col0, int half, float w) {
    float C1[8][4];
    #pragma unroll
    for (int i = 0; i < 8; i++)
        #pragma unroll
        for (int k = 0; k < 4; k++) C1[i][k] = 0.f;
    mm1_32(C1, sb + OFF_X, sb + OFF_P, lane, row0, col0, false);
    const float* bz = reinterpret_cast<const float*>(smem + OFF_BZ) + half * 64;
    int rl4 = lane >> 2, cb = (lane & 3) * 2;
    #pragma unroll
    for (int mt = 0; mt < 2; mt++)
        #pragma unroll
        for (int g = 0; g < 2; g++)
            #pragma unroll
            for (int h = 0; h < 2; h++) {
                int idx = mt * 4 + g * 2 + h;
                int colb = col0 + g * 16 + h * 8 + cb;
                float2 bz2 = *reinterpret_cast<const float2*>(bz + colb);
                int r0 = row0 + mt * 16 + rl4;
                *reinterpret_cast<__half2*>(smem + OFF_SF + r0 * 128 +
                        ((colb * 2) ^ ((r0 & 7) << 4))) =
                    __floats2half2_rn(fmaf(w, C1[idx][0], bz2.x), fmaf(w, C1[idx][1], bz2.y));
                int r1 = r0 + 8;
                *reinterpret_cast<__half2*>(smem + OFF_SF + r1 * 128 +
                        ((colb * 2) ^ ((r1 & 7) << 4))) =
                    __floats2half2_rn(fmaf(w, C1[idx][2], bz2.x), fmaf(w, C1[idx][3], bz2.y));
            }
}

__device__ __forceinline__ void half_scan(char* smem, int tid, int d) {
    if (tid < 128) {
        int bl = tid >> 6, n = tid & 63;
        float aLv = g_aL[d * 64 + n];
        float r = 0.f;
        const uint32_t colx = (uint32_t)(n * 2);
        #pragma unroll
        for (int seg = 0; seg < 4; seg++) {
            float fv[16];
            #pragma unroll
            for (int j = 0; j < 16; j++) {
                int c = seg * 16 + j;
                fv[j] = __half2float(*reinterpret_cast<const __half*>(
                    smem + OFF_SF + (bl * 64 + c) * 128 + (colx ^ ((c & 7) << 4))));
            }
            #pragma unroll
            for (int j = 0; j < 16; j++) {
                int c = seg * 16 + j;
                *reinterpret_cast<__half*>(
                    smem + OFF_SF + (bl * 64 + c) * 128 + (colx ^ ((c & 7) << 4))) =
                    __float2half_rn(r);
                r = fmaf(aLv, r, fv[j]);
            }
        }
    }
}

__device__ __forceinline__ void half_mma2_epi(char* smem, uint32_t sb, int tid, int lane, int wid,
                                              int row0, int col0, int half, int m, int d) {
    float C2[8][4];
    #pragma unroll
    for (int i = 0; i < 8; i++)
        #pragma unroll
        for (int k = 0; k < 4; k++) C2[i][k] = 0.f;
    mm1_32(C2, sb + OFF_X, sb + OFF_M, lane, row0, col0, true);
    mm1_32(C2, sb + OFF_SF, sb + OFF_Q, lane, row0, col0, false);

    const float* beta = reinterpret_cast<const float*>(smem + OFF_BETA) + half * 64;
    int cb = (lane & 3) * 2;
    float ps = 0.f, pm = -3.402823466e38f;
    #pragma unroll
    for (int mt = 0; mt < 2; mt++)
        #pragma unroll
        for (int g = 0; g < 2; g++)
            #pragma unroll
            for (int h = 0; h < 2; h++) {
                int idx = mt * 4 + g * 2 + h;
                float2 b2 = *reinterpret_cast<const float2*>(
                    beta + col0 + g * 16 + h * 8 + cb);
                #pragma unroll
                for (int k = 0; k < 4; k++) {
                    float ypre = C2[idx][k] + ((k & 1) ? b2.y : b2.x);
                    float inner = 0.7978845608028654f * ypre * fmaf(0.044715f, ypre * ypre, 1.0f);
                    float th; asm("tanh.approx.f32 %0, %1;" : "=f"(th) : "f"(inner));
                    float hh = 0.5f * ypre * (1.0f + th);
                    ps += hh;
                    pm = fmaxf(pm, hh);
                }
            }
    #pragma unroll
    for (int o = 16; o > 0; o >>= 1) {
        ps += __shfl_xor_sync(0xffffffffu, ps, o);
        pm = fmaxf(pm, __shfl_xor_sync(0xffffffffu, pm, o));
    }
    float* wp = reinterpret_cast<float*>(smem + OFF_WP);
    if (lane == 0) { wp[wid * 2] = ps; wp[wid * 2 + 1] = pm; }
    __syncthreads();
    if (tid < 2) {
        // batch0: warps 0,1,4,5 (row0<64) ; batch1: warps 2,3,6,7
        int w0 = tid * 2;
        float s = wp[(w0 + 0) * 2] + wp[(w0 + 1) * 2] + wp[(w0 + 4) * 2] + wp[(w0 + 5) * 2];
        float mx = fmaxf(fmaxf(wp[(w0 + 0) * 2 + 1], wp[(w0 + 1) * 2 + 1]),
                         fmaxf(wp[(w0 + 4) * 2 + 1], wp[(w0 + 5) * 2 + 1]));
        int b = m * 2 + tid;
        g_pool[(b * DM + d) * 2] = s;
        g_pool[(b * DM + d) * 2 + 1] = mx;
    }
}

// ---------------- fused SSM: 2 batches x 2 channels per CTA, pipelined + tail head ----------------
__global__ __launch_bounds__(256, 3)
void ssm_mma(const float* __restrict__ w_in, const float* __restrict__ b_in,
             const float* __restrict__ W_head, const float* __restrict__ b_head,
             float* __restrict__ out) {
    extern __shared__ char smem[];
    const uint32_t sb = smem_u32(smem);
    const int tid = threadIdx.x, wid = tid >> 5, lane = tid & 31;
    const int m = blockIdx.x;
    const int d0 = blockIdx.y * 2;         // this CTA handles d0 and d0+1
    const int row0 = (wid & 3) * 32;
    const int col0 = (wid >> 2) * 32;

    if (tid < 128) {   // beta/bz for both halves
        int hh = tid >> 6, nn = tid & 63, dd = d0 + hh;
        reinterpret_cast<float*>(smem + OFF_BETA)[hh * 64 + nn] = g_beta[dd * 64 + nn];
        reinterpret_cast<float*>(smem + OFF_BZ)[hh * 64 + nn] = b_in[dd] * g_zeta[dd * 64 + nn];
    }

    {   // g0: X + P0
        const char* xp = (const char*)g_x + (size_t)m * 16384;
        #pragma unroll
        for (int k = 0; k < 4; k++) {
            int i = (tid + k * 256) * 16;
            CP16(sb + OFF_X + i, xp + i);
        }
        const char* pp = (const char*)g_P + d0 * 8192;
        #pragma unroll
        for (int k = 0; k < 2; k++) {
            int i = (tid + k * 256) * 16;
            CP16(sb + OFF_P + i, pp + i);
        }
        CP_COMMIT();
        // g1: M0 + Q0
        const char* mp = (const char*)g_M + d0 * 8192;
        const char* qp = (const char*)g_Q + d0 * 8192;
        #pragma unroll
        for (int k = 0; k < 2; k++) {
            int i = (tid + k * 256) * 16;
            CP16(sb + OFF_M + i, mp + i);
            CP16(sb + OFF_Q + i, qp + i);
        }
        CP_COMMIT();
    }
    CP_WAIT(1);    // X + P0 landed
    __syncthreads();

    // ======== half 0 (d0) ========
    half_mma1_fstore(smem, sb, lane, wid, row0, col0, 0, w_in[d0]);
    __syncthreads();                       // SF written; P0 reads done
    {   // g2: prefetch P1 into P slot (dead)
        const char* pp = (const char*)g_P + (d0 + 1) * 8192;
        #pragma unroll
        for (int k = 0; k < 2; k++) {
            int i = (tid + k * 256) * 16;
            CP16(sb + OFF_P + i, pp + i);
        }
        CP_COMMIT();
    }
    half_scan(smem, tid, d0);
    CP_WAIT(1);    // M0+Q0 landed (P1 may be in flight)
    __syncthreads();
    half_mma2_epi(smem, sb, tid, lane, wid, row0, col0, 0, m, d0);
    __syncthreads();                       // M0/Q0/SF reads done
    {   // g3: M1 + Q1 into M/Q slots
        const char* mp = (const char*)g_M + (d0 + 1) * 8192;
        const char* qp = (const char*)g_Q + (d0 + 1) * 8192;
        #pragma unroll
        for (int k = 0; k < 2; k++) {
            int i = (tid + k * 256) * 16;
            CP16(sb + OFF_M + i, mp + i);
            CP16(sb + OFF_Q + i, qp + i);
        }
        CP_COMMIT();
    }

    // ======== half 1 (d0+1) ========
    CP_WAIT(1);    // P1 landed (M1+Q1 may be in flight)
    __syncthreads();
    half_mma1_fstore(smem, sb, lane, wid, row0, col0, 1, w_in[d0 + 1]);
    __syncthreads();
    half_scan(smem, tid, d0 + 1);
    CP_WAIT(0);    // M1 + Q1 landed
    __syncthreads();
    half_mma2_epi(smem, sb, tid, lane, wid, row0, col0, 1, m, d0 + 1);

    // ---- last-CTA head ----
    __shared__ unsigned int s_last;
    __threadfence();
    __syncthreads();
    if (tid == 0) {
        unsigned int v = atomicAdd(&g_ctr, 1u);
        s_last = (v == TOTAL_CTAS - 1) ? 1u : 0u;
    }
    __syncthreads();
    if (s_last) {
        __threadfence();   // acquire all pool writes
        #pragma unroll
        for (int bb = 0; bb < 4; bb++) {
            int b = wid * 4 + bb;
            float acc[NCLS];
            #pragma unroll
            for (int k = 0; k < NCLS; k++) acc[k] = 0.f;
            #pragma unroll
            for (int j = 0; j < 16; j++) {
                int dd = lane + j * 32;          // 0..511
                float v;
                if (dd < DM) v = g_pool[(b * DM + dd) * 2] * (1.0f / (float)T_TOTAL);
                else         v = g_pool[(b * DM + (dd - DM)) * 2 + 1];
                #pragma unroll
                for (int k = 0; k < NCLS; k++)
                    acc[k] = fmaf(v, W_head[dd * NCLS + k], acc[k]);
            }
            #pragma unroll
            for (int k = 0; k < NCLS; k++) {
                float v = acc[k];
                #pragma unroll
                for (int o = 16; o > 0; o >>= 1) v += __shfl_xor_sync(0xffffffffu, v, o);
                if (lane == 0) out[b * NCLS + k] = v + b_head[k];
            }
        }
        __syncthreads();
        if (tid == 0) g_ctr = 0;   // reset for next graph replay
    }
}

extern "C" void kernel_launch(void* const* d_in, const int* in_sizes, int n_in,
                              void* d_out, int out_size) {
    const float* x      = (const float*)d_in[0];
    const float* w_in   = (const float*)d_in[1];
    const float* b_in   = (const float*)d_in[2];
    const float* A_diag = (const float*)d_in[3];
    const float* B_in   = (const float*)d_in[4];
    const float* C_out  = (const float*)d_in[5];
    const float* D_skip = (const float*)d_in[6];
    const float* W_head = (const float*)d_in[7];
    const float* b_head = (const float*)d_in[8];
    float* out = (float*)d_out;

    cudaFuncSetAttribute(ssm_mma, cudaFuncAttributeMaxDynamicSharedMemorySize, SMEM_BYTES);
    prep<<<384, 256>>>(x, w_in, b_in, A_diag, B_in, C_out, D_skip);
    ssm_mma<<<dim3(MT, DM / 2), 256, SMEM_BYTES>>>(w_in, b_in, W_head, b_head, out);
}

// round 17
// speedup vs baseline: 1.8559x; 1.0557x over previous
#include <cuda_runtime.h>
#include <cuda_fp16.h>
#include <cstdint>

#define BATCH 32
#define T_TOTAL 4096
#define DM 256
#define SN 64
#define NCLS 5
#define L 64
#define MT 16                  /* 128-row tiles: 2 batches per tile */
#define GRID_CTAS 444          /* persistent: 148 SMs x 3 */
#define N_ITEMS (MT * DM)      /* 4096 work items: (m, d) */

// ---- gmem precomputed operands (pre-swizzled fp16) ----
__device__ __half g_x[BATCH * T_TOTAL];
__device__ __half g_P[DM * 4096];
__device__ __half g_M[DM * 4096];
__device__ __half g_Q[DM * 4096];
__device__ float g_beta[DM * L], g_zeta[DM * SN], g_aL[DM * SN];
__device__ float g_pool[BATCH * DM * 2];
__device__ unsigned int g_ctr = 0;

// ---- smem layout (bytes) for ssm_mma ----
#define OFF_BETA 0                 /* 2 x 64 f32 (parity) */
#define OFF_WP   512               /* 16 f32 */
#define OFF_BZ   576               /* 2 x 64 f32 (parity) */
#define OFF_X    1152              /* 128 x 128B fp16 */
#define OFF_SF   17536             /* f (MMA1 out) then seeds: 128 x 128B */
#define OFF_P0   33920             /* P buffer 0: 64 x 128B */
#define OFF_P1   42112             /* P buffer 1: 64 x 128B */
#define OFF_M    50304             /* 64 x 128B */
#define OFF_Q    58496             /* 64 x 128B */
#define SMEM_BYTES 66688

__device__ __forceinline__ uint32_t smem_u32(const void* p) {
    uint32_t a;
    asm("{ .reg .u64 t; cvta.to.shared.u64 t, %1; cvt.u32.u64 %0, t; }" : "=r"(a) : "l"(p));
    return a;
}
#define CP16(dst, src) asm volatile("cp.async.cg.shared.global [%0], [%1], 16;" :: "r"(dst), "l"(src))
#define CP_COMMIT()    asm volatile("cp.async.commit_group;" ::: "memory")
#define CP_WAIT(n)     asm volatile("cp.async.wait_group %0;" :: "n"(n) : "memory")

__device__ __forceinline__ void ldsm4(uint32_t addr, uint32_t r[4]) {
    asm volatile("ldmatrix.sync.aligned.m8n8.x4.shared.b16 {%0,%1,%2,%3}, [%4];"
                 : "=r"(r[0]), "=r"(r[1]), "=r"(r[2]), "=r"(r[3]) : "r"(addr));
}
__device__ __forceinline__ void mma_f16(float c[4], const uint32_t a[4], uint32_t b0, uint32_t b1) {
    asm volatile("mma.sync.aligned.m16n8k16.row.col.f32.f16.f16.f32 "
                 "{%0,%1,%2,%3}, {%4,%5,%6,%7}, {%8,%9}, {%0,%1,%2,%3};"
                 : "+f"(c[0]), "+f"(c[1]), "+f"(c[2]), "+f"(c[3])
                 : "r"(a[0]), "r"(a[1]), "r"(a[2]), "r"(a[3]), "r"(b0), "r"(b1));
}
// swizzled elem index within a 128B-row fp16 tile
__device__ __forceinline__ int swzi(int row, int col) {
    return ((row * 128 + col * 2) ^ ((row & 7) << 4)) >> 1;
}

// 32x32 warp-tile fp16 matmul-accumulate over K=64. triM: skip zero tiles of lower-tri M'.
__device__ __forceinline__ void mm1_32(float C[8][4], uint32_t aBase, uint32_t bBase,
                                       int lane, int row0, int col0, bool triM) {
    const uint32_t sxor = ((uint32_t)(lane & 7)) << 4;
    const uint32_t ak16 = ((lane >> 4) & 1) * 16;
    const int arowl = lane & 15;
    const int brow = ((lane >> 3) & 2) * 4 + (lane & 7);
    const uint32_t bk16 = ((lane >> 3) & 1) * 16;
    #pragma unroll
    for (int kc = 0; kc < 4; kc++) {
        uint32_t a0[4], a1[4];
        uint32_t acol = (ak16 + kc * 32) ^ sxor;
        ldsm4(aBase + (uint32_t)(row0 + arowl) * 128 + acol, a0);
        ldsm4(aBase + (uint32_t)(row0 + 16 + arowl) * 128 + acol, a1);
        #pragma unroll
        for (int g = 0; g < 2; g++) {
            int cg = col0 + g * 16;
            if (triM && kc * 16 > cg + 15) continue;
            uint32_t b[4];
            ldsm4(bBase + (uint32_t)(cg + brow) * 128 + ((bk16 + kc * 32) ^ sxor), b);
            mma_f16(C[0 + g * 2 + 0], a0, b[0], b[1]);
            mma_f16(C[0 + g * 2 + 1], a0, b[2], b[3]);
            mma_f16(C[4 + g * 2 + 0], a1, b[0], b[1]);
            mma_f16(C[4 + g * 2 + 1], a1, b[2], b[3]);
        }
    }
}

// ---------------- merged prep: x->fp16 swizzle (blocks 0-127) + per-d tiles (128-383) ----------------
__global__ void prep(const float* __restrict__ x,
                     const float* __restrict__ w_in, const float* __restrict__ b_in,
                     const float* __restrict__ A_diag, const float* __restrict__ B_in,
                     const float* __restrict__ C_out, const float* __restrict__ D_skip) {
    const int tid = threadIdx.x;
    if (blockIdx.x < 128) {
        int e = (blockIdx.x * 256 + tid) * 4;
        float4 v = *reinterpret_cast<const float4*>(x + e);
        int b = e >> 12, t = e & 4095;
        int rg = b * 64 + (t >> 6), col = t & 63;
        int boff = rg * 128 + ((col * 2) ^ ((rg & 7) << 4));
        __half2 p0 = __floats2half2_rn(v.x, v.y);
        __half2 p1 = __floats2half2_rn(v.z, v.w);
        char* p = (char*)g_x + boff;
        *(__half2*)p = p0;
        *(__half2*)(p + 4) = p1;
        return;
    }
    const int d = blockIdx.x - 128;
    const int n = tid & 63, q = tid >> 6;
    __shared__ float gmat[64][65];
    __shared__ float Kp[64][4];
    __shared__ float Ksm[64];
    __shared__ float zp[4][64];
    __shared__ __half sP[4096];
    __shared__ __half sQ[4096];

    float a = A_diag[d * 64 + n];
    float g = B_in[d * 64 + n] * C_out[d * 64 + n];
    float a2 = a * a, a4 = a2 * a2, a8 = a4 * a4, a16 = a8 * a8;
    float a32 = a16 * a16, a48 = a32 * a16, a64v = a32 * a32;
    float s = (q == 0) ? 1.f : ((q == 1) ? a16 : ((q == 2) ? a32 : a48));

    {   // P[n][tau] = a^(63-tau); zeta partial
        float p = s, zs = 0.f;
        #pragma unroll
        for (int j = 0; j < 16; j++) {
            int e = q * 16 + j, tau = 63 - e;
            sP[swzi(n, tau)] = __float2half_rn(p);
            zs += p; p *= a;
        }
        zp[q][n] = zs;
    }
    {   // Q[i][n] = g*a^(i+1)
        float t = g * s * a;
        #pragma unroll
        for (int j = 0; j < 16; j++) {
            int i = q * 16 + j;
            sQ[swzi(i, n)] = __float2half_rn(t);
            t *= a;
        }
    }
    {   // gmat[delta][n] = g*a^delta
        float u = g * s;
        #pragma unroll
        for (int j = 0; j < 16; j++) { gmat[q * 16 + j][n] = u; u *= a; }
    }
    __syncthreads();
    {   // coalesced copy-out of P and Q
        const int4* srcP = reinterpret_cast<const int4*>(sP);
        const int4* srcQ = reinterpret_cast<const int4*>(sQ);
        int4* dstP = reinterpret_cast<int4*>(g_P + d * 4096);
        int4* dstQ = reinterpret_cast<int4*>(g_Q + d * 4096);
        #pragma unroll
        for (int k = 0; k < 2; k++) {
            dstP[tid + k * 256] = srcP[tid + k * 256];
            dstQ[tid + k * 256] = srcQ[tid + k * 256];
        }
    }
    if (q == 0) {
        g_zeta[d * 64 + n] = zp[0][n] + zp[1][n] + zp[2][n] + zp[3][n];
        g_aL[d * 64 + n] = a64v;
    }
    {   // K[delta] partial over n
        float ss = 0.f;
        #pragma unroll
        for (int j = 0; j < 16; j++) ss += gmat[n][q * 16 + j];
        Kp[n][q] = ss;
    }
    __syncthreads();
    if (tid < 64) Ksm[tid] = Kp[tid][0] + Kp[tid][1] + Kp[tid][2] + Kp[tid][3];
    __syncthreads();
    float w = w_in[d], bb = b_in[d], dsk = D_skip[d];
    if (tid < 64) {
        float kap = 0.f;
        for (int dd = 0; dd <= tid; dd++) kap += Ksm[dd];
        g_beta[d * 64 + tid] = bb * kap + dsk * bb;
    }
    {   // M[i][tau] = w*K[i-tau] (tau<=i), + dsk*w on diag -> stage into sP (dead)
        int i = n;
        #pragma unroll
        for (int j = 0; j < 16; j++) {
            int tau = q * 16 + j;
            float val = (tau <= i) ? w * Ksm[i - tau] : 0.f;
            if (tau == i) val += dsk * w;
            sP[swzi(i, tau)] = __float2half_rn(val);
        }
    }
    __syncthreads();
    {   // coalesced copy-out of M
        const int4* srcM = reinterpret_cast<const int4*>(sP);
        int4* dstM = reinterpret_cast<int4*>(g_M + d * 4096);
        #pragma unroll
        for (int k = 0; k < 2; k++)
            dstM[tid + k * 256] = srcM[tid + k * 256];
    }
}

// ---------------- per-item building blocks ----------------
__device__ __forceinline__ void item_mma1_fstore(char* smem, uint32_t sb, int lane, int wid,
                                                 int row0, int col0, uint32_t poff, int par, float w) {
    float C1[8][4];
    #pragma unroll
    for (int i = 0; i < 8; i++)
        #pragma unroll
        for (int k = 0; k < 4; k++) C1[i][k] = 0.f;
    mm1_32(C1, sb + OFF_X, sb + poff, lane, row0, col0, false);
    const float* bz = reinterpret_cast<const float*>(smem + OFF_BZ) + par * 64;
    int rl4 = lane >> 2, cb = (lane & 3) * 2;
    #pragma unroll
    for (int mt = 0; mt < 2; mt++)
        #pragma unroll
        for (int g = 0; g < 2; g++)
            #pragma unroll
            for (int h = 0; h < 2; h++) {
                int idx = mt * 4 + g * 2 + h;
                int colb = col0 + g * 16 + h * 8 + cb;
                float2 bz2 = *reinterpret_cast<const float2*>(bz + colb);
                int r0 = row0 + mt * 16 + rl4;
                *reinterpret_cast<__half2*>(smem + OFF_SF + r0 * 128 +
                        ((colb * 2) ^ ((r0 & 7) << 4))) =
                    __floats2half2_rn(fmaf(w, C1[idx][0], bz2.x), fmaf(w, C1[idx][1], bz2.y));
                int r1 = r0 + 8;
                *reinterpret_cast<__half2*>(smem + OFF_SF + r1 * 128 +
                        ((colb * 2) ^ ((r1 & 7) << 4))) =
                    __floats2half2_rn(fmaf(w, C1[idx][2], bz2.x), fmaf(w, C1[idx][3], bz2.y));
            }
}

__device__ __forceinline__ void item_scan(char* smem, int tid, int d) {
    if (tid < 128) {
        int bl = tid >> 6, n = tid & 63;
        float aLv = g_aL[d * 64 + n];
        float r = 0.f;
        const uint32_t colx = (uint32_t)(n * 2);
        #pragma unroll
        for (int seg = 0; seg < 4; seg++) {
            float fv[16];
            #pragma unroll
            for (int j = 0; j < 16; j++) {
                int c = seg * 16 + j;
                fv[j] = __half2float(*reinterpret_cast<const __half*>(
                    smem + OFF_SF + (bl * 64 + c) * 128 + (colx ^ ((c & 7) << 4))));
            }
            #pragma unroll
            for (int j = 0; j < 16; j++) {
                int c = seg * 16 + j;
                *reinterpret_cast<__half*>(
                    smem + OFF_SF + (bl * 64 + c) * 128 + (colx ^ ((c & 7) << 4))) =
                    __float2half_rn(r);
                r = fmaf(aLv, r, fv[j]);
            }
        }
    }
}

__device__ __forceinline__ void item_mma2_epi(char* smem, uint32_t sb, int tid, int lane, int wid,
                                              int row0, int col0, int par, int m, int d) {
    float C2[8][4];
    #pragma unroll
    for (int i = 0; i < 8; i++)
        #pragma unroll
        for (int k = 0; k < 4; k++) C2[i][k] = 0.f;
    mm1_32(C2, sb + OFF_X, sb + OFF_M, lane, row0, col0, true);
    mm1_32(C2, sb + OFF_SF, sb + OFF_Q, lane, row0, col0, false);

    const float* beta = reinterpret_cast<const float*>(smem + OFF_BETA) + par * 64;
    int cb = (lane & 3) * 2;
    float ps = 0.f, pm = -3.402823466e38f;
    #pragma unroll
    for (int mt = 0; mt < 2; mt++)
        #pragma unroll
        for (int g = 0; g < 2; g++)
            #pragma unroll
            for (int h = 0; h < 2; h++) {
                int idx = mt * 4 + g * 2 + h;
                float2 b2 = *reinterpret_cast<const float2*>(
                    beta + col0 + g * 16 + h * 8 + cb);
                #pragma unroll
                for (int k = 0; k < 4; k++) {
                    float ypre = C2[idx][k] + ((k & 1) ? b2.y : b2.x);
                    float inner = 0.7978845608028654f * ypre * fmaf(0.044715f, ypre * ypre, 1.0f);
                    float th; asm("tanh.approx.f32 %0, %1;" : "=f"(th) : "f"(inner));
                    float hh = 0.5f * ypre * (1.0f + th);
                    ps += hh;
                    pm = fmaxf(pm, hh);
                }
            }
    #pragma unroll
    for (int o = 16; o > 0; o >>= 1) {
        ps += __shfl_xor_sync(0xffffffffu, ps, o);
        pm = fmaxf(pm, __shfl_xor_sync(0xffffffffu, pm, o));
    }
    float* wp = reinterpret_cast<float*>(smem + OFF_WP);
    if (lane == 0) { wp[wid * 2] = ps; wp[wid * 2 + 1] = pm; }
    __syncthreads();          // also fences all M/Q/X/SF reads of this item
    if (tid < 2) {
        // batch0: warps 0,1,4,5 (row0<64) ; batch1: warps 2,3,6,7
        int w0 = tid * 2;
        float s = wp[(w0 + 0) * 2] + wp[(w0 + 1) * 2] + wp[(w0 + 4) * 2] + wp[(w0 + 5) * 2];
        float mx = fmaxf(fmaxf(wp[(w0 + 0) * 2 + 1], wp[(w0 + 1) * 2 + 1]),
                         fmaxf(wp[(w0 + 4) * 2 + 1], wp[(w0 + 5) * 2 + 1]));
        int b = m * 2 + tid;
        g_pool[(b * DM + d) * 2] = s;
        g_pool[(b * DM + d) * 2 + 1] = mx;
    }
}

// ---------------- persistent fused SSM + tail head ----------------
__global__ __launch_bounds__(256, 3)
void ssm_mma(const float* __restrict__ w_in, const float* __restrict__ b_in,
             const float* __restrict__ W_head, const float* __restrict__ b_head,
             float* __restrict__ out) {
    extern __shared__ char smem[];
    const uint32_t sb = smem_u32(smem);
    const int tid = threadIdx.x, wid = tid >> 5, lane = tid & 31;
    const int row0 = (wid & 3) * 32;
    const int col0 = (wid >> 2) * 32;

    // static work assignment: items in m-major order, contiguous ranges
    const int cta = blockIdx.x;
    const int start = cta * 9 + min(cta, 100);
    const int cnt = (cta < 100) ? 10 : 9;

    // ---- prologue: prime beta/bz(0), X(m0)+P(0) [group], M(0)+Q(0) [group] ----
    {
        int i0 = start;
        int d0 = i0 & 255, m0 = i0 >> 8;
        if (tid < 64) {
            reinterpret_cast<float*>(smem + OFF_BETA)[tid] = g_beta[d0 * 64 + tid];
            reinterpret_cast<float*>(smem + OFF_BZ)[tid] = b_in[d0] * g_zeta[d0 * 64 + tid];
        }
        const char* xp = (const char*)g_x + (size_t)m0 * 16384;
        #pragma unroll
        for (int k = 0; k < 4; k++) {
            int i = (tid + k * 256) * 16;
            CP16(sb + OFF_X + i, xp + i);
        }
        const char* pp = (const char*)g_P + d0 * 8192;
        #pragma unroll
        for (int k = 0; k < 2; k++) {
            int i = (tid + k * 256) * 16;
            CP16(sb + OFF_P0 + i, pp + i);
        }
        CP_COMMIT();
        const char* mp = (const char*)g_M + d0 * 8192;
        const char* qp = (const char*)g_Q + d0 * 8192;
        #pragma unroll
        for (int k = 0; k < 2; k++) {
            int i = (tid + k * 256) * 16;
            CP16(sb + OFF_M + i, mp + i);
            CP16(sb + OFF_Q + i, qp + i);
        }
        CP_COMMIT();
    }

    int mcur = start >> 8;
    int xpend = 0;     // X restage rides in the newest (MQ) group

    for (int k = 0; k < cnt; k++) {
        const int it = start + k;
        const int dk = it & 255, mk = it >> 8;
        const int par = k & 1;

        if (xpend) { CP_WAIT(0); } else { CP_WAIT(1); }   // drain P(k) (+X if restaged)
        __syncthreads();
        xpend = 0;

        item_mma1_fstore(smem, sb, lane, wid, row0, col0,
                         (uint32_t)(par ? OFF_P1 : OFF_P0), par, w_in[dk]);
        __syncthreads();      // SF f-ready; P(k) reads done

        const int more = (k + 1 < cnt);
        int dn = 0, mn = 0;
        if (more) {
            int in = it + 1;
            dn = in & 255; mn = in >> 8;
            // prefetch P(k+1) into alternate buffer; beta/bz(k+1) into alternate parity
            const char* pp = (const char*)g_P + dn * 8192;
            uint32_t pdst = (uint32_t)(((k + 1) & 1) ? OFF_P1 : OFF_P0);
            #pragma unroll
            for (int kk = 0; kk < 2; kk++) {
                int i = (tid + kk * 256) * 16;
                CP16(sb + pdst + i, pp + i);
            }
            CP_COMMIT();
            if (tid < 64) {
                int np = (k + 1) & 1;
                reinterpret_cast<float*>(smem + OFF_BETA)[np * 64 + tid] = g_beta[dn * 64 + tid];
                reinterpret_cast<float*>(smem + OFF_BZ)[np * 64 + tid] = b_in[dn] * g_zeta[dn * 64 + tid];
            }
        }

        item_scan(smem, tid, dk);

        if (more) { CP_WAIT(1); } else { CP_WAIT(0); }    // drain M/Q(k), keep P(k+1) flying
        __syncthreads();

        item_mma2_epi(smem, sb, tid, lane, wid, row0, col0, par, mk, dk);
        // epi's internal syncthreads guarantees all M/Q/X/SF reads complete

        if (more) {
            const char* mp = (const char*)g_M + dn * 8192;
            const char* qp = (const char*)g_Q + dn * 8192;
            #pragma unroll
            for (int kk = 0; kk < 2; kk++) {
                int i = (tid + kk * 256) * 16;
                CP16(sb + OFF_M + i, mp + i);
                CP16(sb + OFF_Q + i, qp + i);
            }
            if (mn != mcur) {
                const char* xp = (const char*)g_x + (size_t)mn * 16384;
                #pragma unroll
                for (int kk = 0; kk < 4; kk++) {
                    int i = (tid + kk * 256) * 16;
                    CP16(sb + OFF_X + i, xp + i);
                }
                xpend = 1;
                mcur = mn;
            }
            CP_COMMIT();
        }
    }

    // ---- last-CTA head ----
    __shared__ unsigned int s_last;
    __threadfence();
    __syncthreads();
    if (tid == 0) {
        unsigned int v = atomicAdd(&g_ctr, 1u);
        s_last = (v == GRID_CTAS - 1) ? 1u : 0u;
    }
    __syncthreads();
    if (s_last) {
        __threadfence();   // acquire all pool writes
        #pragma unroll
        for (int bb = 0; bb < 4; bb++) {
            int b = wid * 4 + bb;
            float acc[NCLS];
            #pragma unroll
            for (int k = 0; k < NCLS; k++) acc[k] = 0.f;
            #pragma unroll
            for (int j = 0; j < 16; j++) {
                int dd = lane + j * 32;          // 0..511
                float v;
                if (dd < DM) v = g_pool[(b * DM + dd) * 2] * (1.0f / (float)T_TOTAL);
                else         v = g_pool[(b * DM + (dd - DM)) * 2 + 1];
                #pragma unroll
                for (int k = 0; k < NCLS; k++)
                    acc[k] = fmaf(v, W_head[dd * NCLS + k], acc[k]);
            }
            #pragma unroll
            for (int k = 0; k < NCLS; k++) {
                float v = acc[k];
                #pragma unroll
                for (int o = 16; o > 0; o >>= 1) v += __shfl_xor_sync(0xffffffffu, v, o);
                if (lane == 0) out[b * NCLS + k] = v + b_head[k];
            }
        }
        __syncthreads();
        if (tid == 0) g_ctr = 0;   // reset for next graph replay
    }
}

extern "C" void kernel_launch(void* const* d_in, const int* in_sizes, int n_in,
                              void* d_out, int out_size) {
    const float* x      = (const float*)d_in[0];
    const float* w_in   = (const float*)d_in[1];
    const float* b_in   = (const float*)d_in[2];
    const float* A_diag = (const float*)d_in[3];
    const float* B_in   = (const float*)d_in[4];
    const float* C_out  = (const float*)d_in[5];
    const float* D_skip = (const float*)d_in[6];
    const float* W_head = (const float*)d_in[7];
    const float* b_head = (const float*)d_in[8];
    float* out = (float*)d_out;

    cudaFuncSetAttribute(ssm_mma, cudaFuncAttributeMaxDynamicSharedMemorySize, SMEM_BYTES);
    prep<<<384, 256>>>(x, w_in, b_in, A_diag, B_in, C_out, D_skip);
    ssm_mma<<<GRID_CTAS, 256, SMEM_BYTES>>>(w_in, b_in, W_head, b_head, out);
}